// round 2
// baseline (speedup 1.0000x reference)
#include <cuda_runtime.h>
#include <cuda_bf16.h>

#define NRES 4096
#define KNB  48
#define EDIM 128
#define DFEAT 416
#define NEDGE (NRES*KNB)   // 196608

// ---------------- scratch (static device globals: allowed) ----------------
__device__ float g_bb[NRES * 15];          // [n, ca, c, o, cb] x 3
__device__ float g_ca[NRES * 3];           // SoA: x[N], y[N], z[N]
__device__ int   g_idx[NEDGE];
__device__ float g_edges[(long long)NEDGE * DFEAT];  // 327 MB
__device__ float g_eln[(long long)NEDGE * EDIM];     // 100 MB

// ---------------- helpers ----------------
__device__ __forceinline__ unsigned long long pack2(float a, float b) {
    unsigned long long r;
    asm("mov.b64 %0, {%1, %2};" : "=l"(r) : "f"(a), "f"(b));
    return r;
}
__device__ __forceinline__ void unpack2(unsigned long long v, float& a, float& b) {
    asm("mov.b64 {%0, %1}, %2;" : "=f"(a), "=f"(b) : "l"(v));
}
__device__ __forceinline__ unsigned long long fma2(unsigned long long a,
                                                   unsigned long long b,
                                                   unsigned long long c) {
    unsigned long long d;
    asm("fma.rn.f32x2 %0, %1, %2, %3;" : "=l"(d) : "l"(a), "l"(b), "l"(c));
    return d;
}

// exp(x) for x <= 0, pure FMA/ALU pipe (no MUFU). rel err ~1e-8.
__device__ __forceinline__ float fexp(float x) {
    const float L2E = 1.4426950408889634f;
    x = fmaxf(x, -87.0f);
    float y  = x * L2E;
    float z  = y + 12582912.0f;            // round-to-nearest via magic number
    float nf = z - 12582912.0f;
    float f  = y - nf;
    float g  = f * 0.6931471805599453f;    // |g| <= 0.347
    float p  = fmaf(g, 1.0f/720.0f, 1.0f/120.0f);
    p = fmaf(g, p, 1.0f/24.0f);
    p = fmaf(g, p, 1.0f/6.0f);
    p = fmaf(g, p, 0.5f);
    p = fmaf(g, p, 1.0f);
    p = fmaf(g, p, 1.0f);
    int n = __float_as_int(z) - 0x4B400000;
    float sc = __int_as_float((n + 127) << 23);
    return sc * p;
}

// ---------------- kernel 1: backbone ----------------
__global__ void k_backbone(const float* __restrict__ coords) {
    int i = blockIdx.x * blockDim.x + threadIdx.x;
    if (i >= NRES) return;
    const float* p = coords + i * 12;
    float n0=p[0],n1=p[1],n2=p[2];
    float a0=p[3],a1=p[4],a2=p[5];
    float c0=p[6],c1=p[7],c2=p[8];
    float o0=p[9],o1=p[10],o2=p[11];
    float b0=a0-n0, b1=a1-n1, b2=a2-n2;
    float d0=c0-a0, d1=c1-a1, d2=c2-a2;
    float x0 = b1*d2 - b2*d1;
    float x1 = b2*d0 - b0*d2;
    float x2 = b0*d1 - b1*d0;
    float cb0 = -0.58273431f*x0 + 0.56802827f*b0 - 0.54067466f*d0 + a0;
    float cb1 = -0.58273431f*x1 + 0.56802827f*b1 - 0.54067466f*d1 + a1;
    float cb2 = -0.58273431f*x2 + 0.56802827f*b2 - 0.54067466f*d2 + a2;
    float* q = g_bb + i * 15;
    q[0]=n0; q[1]=n1; q[2]=n2;
    q[3]=a0; q[4]=a1; q[5]=a2;
    q[6]=c0; q[7]=c1; q[8]=c2;
    q[9]=o0; q[10]=o1; q[11]=o2;
    q[12]=cb0; q[13]=cb1; q[14]=cb2;
    g_ca[i] = a0; g_ca[NRES + i] = a1; g_ca[2*NRES + i] = a2;
}

// ---------------- kernel 2: exact 48-NN (stable ties like lax.top_k) ----------------
__global__ __launch_bounds__(256) void k_topk(const float* __restrict__ mask,
                                              float* __restrict__ out_idx) {
    __shared__ float sd[NRES];
    __shared__ unsigned long long sred[8];
    int i = blockIdx.x;
    int tid = threadIdx.x;
    float cax = g_ca[i], cay = g_ca[NRES + i], caz = g_ca[2*NRES + i];
    float mi = mask[i];
    for (int j = tid; j < NRES; j += 256) {
        float dx = __fsub_rn(cax, g_ca[j]);
        float dy = __fsub_rn(cay, g_ca[NRES + j]);
        float dz = __fsub_rn(caz, g_ca[2*NRES + j]);
        float d2 = __fadd_rn(__fadd_rn(__fmul_rn(dx,dx), __fmul_rn(dy,dy)), __fmul_rn(dz,dz));
        float dist = __fsqrt_rn(__fadd_rn(d2, 1e-6f));
        if (__fmul_rn(mi, mask[j]) == 0.0f) dist = __int_as_float(0x7f800000);
        sd[j] = dist;
    }
    __syncthreads();
    int lane = tid & 31, wid = tid >> 5;
    for (int k = 0; k < KNB; k++) {
        unsigned long long best = 0xffffffffffffffffULL;
        for (int j = tid; j < NRES; j += 256) {
            unsigned long long key =
                ((unsigned long long)__float_as_uint(sd[j]) << 32) | (unsigned)j;
            if (key < best) best = key;
        }
        #pragma unroll
        for (int off = 16; off; off >>= 1) {
            unsigned long long o = __shfl_down_sync(0xffffffffu, best, off);
            if (o < best) best = o;
        }
        if (lane == 0) sred[wid] = best;
        __syncthreads();
        if (tid == 0) {
            unsigned long long b = sred[0];
            #pragma unroll
            for (int w = 1; w < 8; w++) if (sred[w] < b) b = sred[w];
            int j = (int)(b & 0xffffffffULL);
            g_idx[i * KNB + k] = j;
            if (out_idx) out_idx[i * KNB + k] = (float)j;
            sd[j] = __int_as_float(0x7f800000);
        }
        __syncthreads();
    }
}

// ---------------- kernel 3: edge features (one warp per edge) ----------------
__global__ __launch_bounds__(256) void k_feat(const int* __restrict__ ri,
                                              const int* __restrict__ ci,
                                              const float* __restrict__ wpw,
                                              const float* __restrict__ wpb) {
    __shared__ float spd[8][32];
    int gw = (blockIdx.x * 256 + threadIdx.x) >> 5;
    if (gw >= NEDGE) return;
    int lane = threadIdx.x & 31;
    int wIn = threadIdx.x >> 5;
    int i = gw / KNB;
    int j = g_idx[gw];

    if (lane < 25) {
        int a = lane / 5, b = lane % 5;
        float dx = g_bb[i*15 + a*3 + 0] - g_bb[j*15 + b*3 + 0];
        float dy = g_bb[i*15 + a*3 + 1] - g_bb[j*15 + b*3 + 1];
        float dz = g_bb[i*15 + a*3 + 2] - g_bb[j*15 + b*3 + 2];
        spd[wIn][lane] = __fsqrt_rn(dx*dx + dy*dy + dz*dz + 1e-6f);
    }
    __syncwarp();

    float* dst = g_edges + (long long)gw * DFEAT;
    if (lane < 16) {
        int ro = ri[i] - ri[j];
        int enc = (ci[i] == ci[j]) ? min(max(ro + 16, 0), 32) : 33;
        dst[lane] = wpw[lane * 34 + enc] + wpb[lane];
    }
    #pragma unroll
    for (int f = 16 + lane; f < DFEAT; f += 32) {
        int r = f - 16;
        float pd = spd[wIn][r >> 4];
        int bin = r & 15;
        float mu = 2.0f + 1.3333334f * (float)bin;   // linspace(2,22,16) step in fp32
        float t = (pd - mu) * 0.8f;                  // sigma = 1.25
        dst[f] = fexp(-t * t);
    }
}

// ---------------- kernel 4: GEMM1 (edges@W^T) + LayerNorm -> g_eln ----------------
__global__ __launch_bounds__(128) void k_gemm1(const float* __restrict__ Bg,
                                               const float* __restrict__ lnw,
                                               const float* __restrict__ lnb) {
    __shared__ float sA[64][33];    // [edge][kk]
    __shared__ float sB[128][33];   // [chan][kk]
    int tid = threadIdx.x;
    int tc = tid & 15, er = tid >> 4;
    long long e0 = (long long)blockIdx.x * 64;

    unsigned long long acc[4][8];
    #pragma unroll
    for (int p = 0; p < 4; p++)
        #pragma unroll
        for (int jj = 0; jj < 8; jj++) acc[p][jj] = 0ULL;

    for (int chn = 0; chn < 13; chn++) {
        int k0 = chn * 32;
        #pragma unroll
        for (int t = 0; t < 16; t++) {
            int lin = tid + 128 * t;
            sA[lin >> 5][lin & 31] = g_edges[(e0 + (lin >> 5)) * DFEAT + k0 + (lin & 31)];
        }
        #pragma unroll
        for (int t = 0; t < 32; t++) {
            int lin = tid + 128 * t;
            sB[lin >> 5][lin & 31] = Bg[(lin >> 5) * DFEAT + k0 + (lin & 31)];
        }
        __syncthreads();
        #pragma unroll 4
        for (int kk = 0; kk < 32; kk++) {
            float a[8], b[8];
            #pragma unroll
            for (int ii = 0; ii < 8; ii++) a[ii] = sA[er * 8 + ii][kk];
            #pragma unroll
            for (int jj = 0; jj < 8; jj++) b[jj] = sB[tc + 16 * jj][kk];
            unsigned long long a2[4], b2[8];
            #pragma unroll
            for (int p = 0; p < 4; p++) a2[p] = pack2(a[2*p], a[2*p + 1]);
            #pragma unroll
            for (int jj = 0; jj < 8; jj++) b2[jj] = pack2(b[jj], b[jj]);
            #pragma unroll
            for (int p = 0; p < 4; p++)
                #pragma unroll
                for (int jj = 0; jj < 8; jj++)
                    acc[p][jj] = fma2(a2[p], b2[jj], acc[p][jj]);
        }
        __syncthreads();
    }

    // LayerNorm over 128 channels per edge (reduce across tc lanes 0..15)
    float s[8], s2[8];
    #pragma unroll
    for (int ii = 0; ii < 8; ii++) { s[ii] = 0.f; s2[ii] = 0.f; }
    #pragma unroll
    for (int p = 0; p < 4; p++)
        #pragma unroll
        for (int jj = 0; jj < 8; jj++) {
            float lo, hi; unpack2(acc[p][jj], lo, hi);
            s[2*p]   += lo; s2[2*p]   += lo * lo;
            s[2*p+1] += hi; s2[2*p+1] += hi * hi;
        }
    #pragma unroll
    for (int off = 1; off < 16; off <<= 1) {
        #pragma unroll
        for (int ii = 0; ii < 8; ii++) {
            s[ii]  += __shfl_xor_sync(0xffffffffu, s[ii],  off);
            s2[ii] += __shfl_xor_sync(0xffffffffu, s2[ii], off);
        }
    }
    float mean[8], rstd[8];
    #pragma unroll
    for (int ii = 0; ii < 8; ii++) {
        mean[ii] = s[ii] * (1.0f / 128.0f);
        float var = s2[ii] * (1.0f / 128.0f) - mean[ii] * mean[ii];
        rstd[ii] = rsqrtf(var + 1e-5f);
    }
    #pragma unroll
    for (int jj = 0; jj < 8; jj++) {
        int c = tc + 16 * jj;
        float w = lnw[c], bo = lnb[c];
        #pragma unroll
        for (int p = 0; p < 4; p++) {
            float lo, hi; unpack2(acc[p][jj], lo, hi);
            int iL = 2*p, iH = 2*p + 1;
            g_eln[(e0 + er*8 + iL) * EDIM + c] = (lo - mean[iL]) * rstd[iL] * w + bo;
            g_eln[(e0 + er*8 + iH) * EDIM + c] = (hi - mean[iH]) * rstd[iH] * w + bo;
        }
    }
}

// ---------------- kernel 5: GEMM2 (eln@proj^T + bias) -> out ----------------
__global__ __launch_bounds__(128) void k_gemm2(const float* __restrict__ Bg,
                                               const float* __restrict__ bias,
                                               float* __restrict__ out) {
    __shared__ float sA[64][33];
    __shared__ float sB[128][33];
    int tid = threadIdx.x;
    int tc = tid & 15, er = tid >> 4;
    long long e0 = (long long)blockIdx.x * 64;

    unsigned long long acc[4][8];
    #pragma unroll
    for (int p = 0; p < 4; p++)
        #pragma unroll
        for (int jj = 0; jj < 8; jj++) acc[p][jj] = 0ULL;

    for (int chn = 0; chn < 4; chn++) {
        int k0 = chn * 32;
        #pragma unroll
        for (int t = 0; t < 16; t++) {
            int lin = tid + 128 * t;
            sA[lin >> 5][lin & 31] = g_eln[(e0 + (lin >> 5)) * EDIM + k0 + (lin & 31)];
        }
        #pragma unroll
        for (int t = 0; t < 32; t++) {
            int lin = tid + 128 * t;
            sB[lin >> 5][lin & 31] = Bg[(lin >> 5) * EDIM + k0 + (lin & 31)];
        }
        __syncthreads();
        #pragma unroll 4
        for (int kk = 0; kk < 32; kk++) {
            float a[8], b[8];
            #pragma unroll
            for (int ii = 0; ii < 8; ii++) a[ii] = sA[er * 8 + ii][kk];
            #pragma unroll
            for (int jj = 0; jj < 8; jj++) b[jj] = sB[tc + 16 * jj][kk];
            unsigned long long a2[4], b2[8];
            #pragma unroll
            for (int p = 0; p < 4; p++) a2[p] = pack2(a[2*p], a[2*p + 1]);
            #pragma unroll
            for (int jj = 0; jj < 8; jj++) b2[jj] = pack2(b[jj], b[jj]);
            #pragma unroll
            for (int p = 0; p < 4; p++)
                #pragma unroll
                for (int jj = 0; jj < 8; jj++)
                    acc[p][jj] = fma2(a2[p], b2[jj], acc[p][jj]);
        }
        __syncthreads();
    }

    #pragma unroll
    for (int jj = 0; jj < 8; jj++) {
        int f = tc + 16 * jj;
        float bv = bias[f];
        #pragma unroll
        for (int p = 0; p < 4; p++) {
            float lo, hi; unpack2(acc[p][jj], lo, hi);
            out[(e0 + er*8 + 2*p    ) * EDIM + f] = lo + bv;
            out[(e0 + er*8 + 2*p + 1) * EDIM + f] = hi + bv;
        }
    }
}

// ---------------- launch ----------------
extern "C" void kernel_launch(void* const* d_in, const int* in_sizes, int n_in,
                              void* d_out, int out_size) {
    const float* coords = (const float*)d_in[0];
    const float* mask   = (const float*)d_in[1];
    const int*   ri     = (const int*)d_in[2];
    const int*   ci     = (const int*)d_in[3];
    const float* wpw    = (const float*)d_in[4];
    const float* wpb    = (const float*)d_in[5];
    const float* wew    = (const float*)d_in[6];
    const float* lnw    = (const float*)d_in[7];
    const float* lnb    = (const float*)d_in[8];
    const float* pw     = (const float*)d_in[9];
    const float* pb     = (const float*)d_in[10];
    float* out = (float*)d_out;

    long long main_elems = (long long)NEDGE * EDIM;   // 25,165,824
    float* out_idx = ((long long)out_size > main_elems) ? (out + main_elems) : nullptr;

    k_backbone<<<(NRES + 255) / 256, 256>>>(coords);
    k_topk<<<NRES, 256>>>(mask, out_idx);
    k_feat<<<(NEDGE * 32) / 256, 256>>>(ri, ci, wpw, wpb);
    k_gemm1<<<NEDGE / 64, 128>>>(wew, lnw, lnb);
    k_gemm2<<<NEDGE / 64, 128>>>(pw, pb, out);
}

// round 4
// speedup vs baseline: 1.0708x; 1.0708x over previous
#include <cuda_runtime.h>
#include <cstdint>

#define NRES 4096
#define KNB  48
#define EDIM 128
#define DFEAT 416
#define NEDGE (NRES*KNB)   // 196608
#define NC1 13             // 416/32 K-chunks for GEMM1
#define NC2 4              // 128/32 K-chunks for GEMM2

// ---------------- device-global scratch ----------------
__device__ float g_bb[NRES * 15];
__device__ float g_ca[NRES * 3];
__device__ int   g_idx[NEDGE];
__device__ float g_edges[(long long)NEDGE * DFEAT];   // 327 MB
// pre-split tf32 weights in m16n8k8 B-fragment layout:
// index = ((chunk*16 + nt)*2 + r)*128 + lane*4 + ks
__device__ float g_B1hi[NC1 * 4096], g_B1lo[NC1 * 4096];
__device__ float g_B2hi[NC2 * 4096], g_B2lo[NC2 * 4096];
__device__ float g_pbfold[EDIM];                      // pb + pw @ lnb

// ---------------- helpers ----------------
__device__ __forceinline__ uint32_t f2tf(float v) {
    uint32_t r;
    asm("cvt.rna.tf32.f32 %0, %1;" : "=r"(r) : "f"(v));
    return r;
}
__device__ __forceinline__ uint32_t smaddr(const void* p) {
    return (uint32_t)__cvta_generic_to_shared(p);
}
#define CP16(dst, src) \
    asm volatile("cp.async.cg.shared.global [%0], [%1], 16;" :: "r"(dst), "l"(src))
#define CP_COMMIT() asm volatile("cp.async.commit_group;" ::: "memory")
#define CP_WAIT(n)  asm volatile("cp.async.wait_group %0;" :: "n"(n) : "memory")

__device__ __forceinline__ void mma8(float* d, uint32_t a0, uint32_t a1,
                                     uint32_t a2, uint32_t a3,
                                     uint32_t b0, uint32_t b1) {
    asm volatile(
        "mma.sync.aligned.m16n8k8.row.col.f32.tf32.tf32.f32 "
        "{%0,%1,%2,%3}, {%4,%5,%6,%7}, {%8,%9}, {%0,%1,%2,%3};"
        : "+f"(d[0]), "+f"(d[1]), "+f"(d[2]), "+f"(d[3])
        : "r"(a0), "r"(a1), "r"(a2), "r"(a3), "r"(b0), "r"(b1));
}

// exp(x), x<=0, pure FMA pipe
__device__ __forceinline__ float fexp(float x) {
    x = fmaxf(x, -87.0f);
    float y  = x * 1.4426950408889634f;
    float z  = y + 12582912.0f;
    float nf = z - 12582912.0f;
    float g  = (y - nf) * 0.6931471805599453f;
    float p  = fmaf(g, 1.0f/720.0f, 1.0f/120.0f);
    p = fmaf(g, p, 1.0f/24.0f);
    p = fmaf(g, p, 1.0f/6.0f);
    p = fmaf(g, p, 0.5f);
    p = fmaf(g, p, 1.0f);
    p = fmaf(g, p, 1.0f);
    int n = __float_as_int(z) - 0x4B400000;
    return __int_as_float((n + 127) << 23) * p;
}

// ---------------- kernel 1: backbone ----------------
__global__ void k_backbone(const float* __restrict__ coords) {
    int i = blockIdx.x * blockDim.x + threadIdx.x;
    if (i >= NRES) return;
    const float* p = coords + i * 12;
    float n0=p[0],n1=p[1],n2=p[2];
    float a0=p[3],a1=p[4],a2=p[5];
    float c0=p[6],c1=p[7],c2=p[8];
    float o0=p[9],o1=p[10],o2=p[11];
    float b0=a0-n0, b1=a1-n1, b2=a2-n2;
    float d0=c0-a0, d1=c1-a1, d2=c2-a2;
    float x0 = b1*d2 - b2*d1;
    float x1 = b2*d0 - b0*d2;
    float x2 = b0*d1 - b1*d0;
    float cb0 = -0.58273431f*x0 + 0.56802827f*b0 - 0.54067466f*d0 + a0;
    float cb1 = -0.58273431f*x1 + 0.56802827f*b1 - 0.54067466f*d1 + a1;
    float cb2 = -0.58273431f*x2 + 0.56802827f*b2 - 0.54067466f*d2 + a2;
    float* q = g_bb + i * 15;
    q[0]=n0; q[1]=n1; q[2]=n2;
    q[3]=a0; q[4]=a1; q[5]=a2;
    q[6]=c0; q[7]=c1; q[8]=c2;
    q[9]=o0; q[10]=o1; q[11]=o2;
    q[12]=cb0; q[13]=cb1; q[14]=cb2;
    g_ca[i] = a0; g_ca[NRES + i] = a1; g_ca[2*NRES + i] = a2;
}

// ---------------- kernel 2: exact 48-NN (stable ties like lax.top_k) ----------------
__global__ __launch_bounds__(256) void k_topk(const float* __restrict__ mask,
                                              float* __restrict__ out_idx) {
    __shared__ float sd[NRES];
    __shared__ unsigned long long sred[8];
    int i = blockIdx.x;
    int tid = threadIdx.x;
    float cax = g_ca[i], cay = g_ca[NRES + i], caz = g_ca[2*NRES + i];
    float mi = mask[i];
    for (int j = tid; j < NRES; j += 256) {
        float dx = __fsub_rn(cax, g_ca[j]);
        float dy = __fsub_rn(cay, g_ca[NRES + j]);
        float dz = __fsub_rn(caz, g_ca[2*NRES + j]);
        float d2 = __fadd_rn(__fadd_rn(__fmul_rn(dx,dx), __fmul_rn(dy,dy)), __fmul_rn(dz,dz));
        float dist = __fsqrt_rn(__fadd_rn(d2, 1e-6f));
        if (__fmul_rn(mi, mask[j]) == 0.0f) dist = __int_as_float(0x7f800000);
        sd[j] = dist;
    }
    __syncthreads();
    int lane = tid & 31, wid = tid >> 5;
    for (int k = 0; k < KNB; k++) {
        unsigned long long best = 0xffffffffffffffffULL;
        for (int j = tid; j < NRES; j += 256) {
            unsigned long long key =
                ((unsigned long long)__float_as_uint(sd[j]) << 32) | (unsigned)j;
            if (key < best) best = key;
        }
        #pragma unroll
        for (int off = 16; off; off >>= 1) {
            unsigned long long o = __shfl_down_sync(0xffffffffu, best, off);
            if (o < best) best = o;
        }
        if (lane == 0) sred[wid] = best;
        __syncthreads();
        if (tid == 0) {
            unsigned long long b = sred[0];
            #pragma unroll
            for (int w = 1; w < 8; w++) if (sred[w] < b) b = sred[w];
            int j = (int)(b & 0xffffffffULL);
            g_idx[i * KNB + k] = j;
            if (out_idx) out_idx[i * KNB + k] = (float)j;
            sd[j] = __int_as_float(0x7f800000);
        }
        __syncthreads();
    }
}

// ---------------- kernel 3: edge features -> g_edges (one warp per edge) ----------------
__global__ __launch_bounds__(256) void k_feat(const int* __restrict__ ri,
                                              const int* __restrict__ ci,
                                              const float* __restrict__ wpw,
                                              const float* __restrict__ wpb) {
    __shared__ float spd[8][32];
    int gw = (blockIdx.x * 256 + threadIdx.x) >> 5;
    if (gw >= NEDGE) return;
    int lane = threadIdx.x & 31;
    int wIn = threadIdx.x >> 5;
    int i = gw / KNB;
    int j = g_idx[gw];

    if (lane < 25) {
        int a = lane / 5, b = lane % 5;
        float dx = g_bb[i*15 + a*3 + 0] - g_bb[j*15 + b*3 + 0];
        float dy = g_bb[i*15 + a*3 + 1] - g_bb[j*15 + b*3 + 1];
        float dz = g_bb[i*15 + a*3 + 2] - g_bb[j*15 + b*3 + 2];
        spd[wIn][lane] = __fsqrt_rn(dx*dx + dy*dy + dz*dz + 1e-6f);
    }
    __syncwarp();

    float* dst = g_edges + (long long)gw * DFEAT;
    if (lane < 16) {
        int ro = ri[i] - ri[j];
        int enc = (ci[i] == ci[j]) ? min(max(ro + 16, 0), 32) : 33;
        dst[lane] = wpw[lane * 34 + enc] + wpb[lane];
    }
    #pragma unroll
    for (int f = 16 + lane; f < DFEAT; f += 32) {
        int r = f - 16;
        float pd = spd[wIn][r >> 4];
        int bin = r & 15;
        float mu = 2.0f + 1.3333334f * (float)bin;
        float t = (pd - mu) * 0.8f;
        dst[f] = fexp(-t * t);
    }
}

// ---------------- kernel 4: weight prep (split + fragment pack + folds) ----------------
__global__ __launch_bounds__(256) void k_prep(const float* __restrict__ wew,
                                              const float* __restrict__ pw,
                                              const float* __restrict__ lnw,
                                              const float* __restrict__ lnb,
                                              const float* __restrict__ pb) {
    int t = blockIdx.x * 256 + threadIdx.x;
    if (t < NC1 * 4096) {
        int c = t >> 12, w = t & 4095;
        int ks = w & 3, lane = (w >> 2) & 31, r = (w >> 7) & 1, nt = w >> 8;
        int n = nt * 8 + (lane >> 2);
        int k = c * 32 + ks * 8 + (lane & 3) + 4 * r;
        float v = wew[n * DFEAT + k];
        float hi = __uint_as_float(f2tf(v));
        g_B1hi[t] = hi;
        g_B1lo[t] = __uint_as_float(f2tf(v - hi));
    } else if (t < (NC1 + NC2) * 4096) {
        int t2 = t - NC1 * 4096;
        int c = t2 >> 12, w = t2 & 4095;
        int ks = w & 3, lane = (w >> 2) & 31, r = (w >> 7) & 1, nt = w >> 8;
        int n = nt * 8 + (lane >> 2);
        int k = c * 32 + ks * 8 + (lane & 3) + 4 * r;
        float v = pw[n * EDIM + k] * lnw[k];      // fold ln scale into proj
        float hi = __uint_as_float(f2tf(v));
        g_B2hi[t2] = hi;
        g_B2lo[t2] = __uint_as_float(f2tf(v - hi));
    } else if (t < (NC1 + NC2) * 4096 + EDIM) {
        int f = t - (NC1 + NC2) * 4096;
        float s = pb[f];
        for (int k = 0; k < EDIM; k++) s += pw[f * EDIM + k] * lnb[k];
        g_pbfold[f] = s;
    }
}

// ---------------- kernel 5: fused HMMA GEMM1 + LN + GEMM2 ----------------
// smem (floats): sA[2][128*36]=9216, sB[2][8192]=16384, sA2[128*132]=16896
#define SA_OFF 0
#define SB_OFF 9216
#define SA2_OFF 25600
#define SM_FLOATS 42496    // 169984 bytes

__global__ __launch_bounds__(256) void k_fused(float* __restrict__ out) {
    extern __shared__ float sm[];
    float* sA  = sm + SA_OFF;
    float* sB  = sm + SB_OFF;
    float* sA2 = sm + SA2_OFF;
    int tid = threadIdx.x, lane = tid & 31, warp = tid >> 5;
    int g = lane >> 2, t = lane & 3;
    long long e0 = (long long)blockIdx.x * 128;

    auto stageA = [&](int c, int b) {
        const float* src = g_edges + e0 * DFEAT + c * 32;
        #pragma unroll
        for (int q = 0; q < 4; q++) {
            int idx = tid + 256 * q;
            int row = idx >> 3, c4 = idx & 7;
            CP16(smaddr(sA + b * 4608 + row * 36 + c4 * 4),
                 src + (long long)row * DFEAT + c4 * 4);
        }
    };
    auto stageB = [&](const float* hi, const float* lo, int c, int b) {
        #pragma unroll
        for (int q = 0; q < 4; q++) {
            int idx = (tid + 256 * q) * 4;
            CP16(smaddr(sB + b * 8192 + idx),        hi + c * 4096 + idx);
            CP16(smaddr(sB + b * 8192 + 4096 + idx), lo + c * 4096 + idx);
        }
    };

    float acc[16][4];
    #pragma unroll
    for (int nt = 0; nt < 16; nt++)
        #pragma unroll
        for (int q = 0; q < 4; q++) acc[nt][q] = 0.0f;

    // ================= GEMM1: 13 chunks, A from g_edges =================
    stageA(0, 0); stageB(g_B1hi, g_B1lo, 0, 0); CP_COMMIT();
    for (int c = 0; c < NC1; c++) {
        int b = c & 1;
        if (c + 1 < NC1) {
            stageA(c + 1, b ^ 1); stageB(g_B1hi, g_B1lo, c + 1, b ^ 1);
            CP_COMMIT(); CP_WAIT(1);
        } else {
            CP_WAIT(0);
        }
        __syncthreads();

        uint32_t ahi[4][4], alo[4][4];
        const float* ar0 = sA + b * 4608 + (warp * 16 + g) * 36;
        const float* ar1 = ar0 + 8 * 36;
        #pragma unroll
        for (int ks = 0; ks < 4; ks++) {
            float v0 = ar0[ks*8 + t],     v1 = ar1[ks*8 + t];
            float v2 = ar0[ks*8 + t + 4], v3 = ar1[ks*8 + t + 4];
            ahi[ks][0] = f2tf(v0); alo[ks][0] = f2tf(v0 - __uint_as_float(ahi[ks][0]));
            ahi[ks][1] = f2tf(v1); alo[ks][1] = f2tf(v1 - __uint_as_float(ahi[ks][1]));
            ahi[ks][2] = f2tf(v2); alo[ks][2] = f2tf(v2 - __uint_as_float(ahi[ks][2]));
            ahi[ks][3] = f2tf(v3); alo[ks][3] = f2tf(v3 - __uint_as_float(ahi[ks][3]));
        }
        const float4* bh4 = (const float4*)(sB + b * 8192);
        const float4* bl4 = (const float4*)(sB + b * 8192 + 4096);
        #pragma unroll
        for (int nt = 0; nt < 16; nt++) {
            float h0[4], h1[4], l0[4], l1[4];
            *(float4*)h0 = bh4[nt*64 + lane];
            *(float4*)h1 = bh4[nt*64 + 32 + lane];
            *(float4*)l0 = bl4[nt*64 + lane];
            *(float4*)l1 = bl4[nt*64 + 32 + lane];
            #pragma unroll
            for (int ks = 0; ks < 4; ks++) {
                uint32_t bh0 = __float_as_uint(h0[ks]), bh1 = __float_as_uint(h1[ks]);
                uint32_t bl0 = __float_as_uint(l0[ks]), bl1 = __float_as_uint(l1[ks]);
                mma8(acc[nt], ahi[ks][0], ahi[ks][1], ahi[ks][2], ahi[ks][3], bh0, bh1);
                mma8(acc[nt], ahi[ks][0], ahi[ks][1], ahi[ks][2], ahi[ks][3], bl0, bl1);
                mma8(acc[nt], alo[ks][0], alo[ks][1], alo[ks][2], alo[ks][3], bh0, bh1);
            }
        }
        __syncthreads();
    }

    // ================= LayerNorm (params folded into GEMM2) =================
    {
        float s0 = 0.f, q0 = 0.f, s1 = 0.f, q1 = 0.f;
        #pragma unroll
        for (int nt = 0; nt < 16; nt++) {
            s0 += acc[nt][0] + acc[nt][1];
            q0 += acc[nt][0]*acc[nt][0] + acc[nt][1]*acc[nt][1];
            s1 += acc[nt][2] + acc[nt][3];
            q1 += acc[nt][2]*acc[nt][2] + acc[nt][3]*acc[nt][3];
        }
        #pragma unroll
        for (int off = 1; off <= 2; off <<= 1) {
            s0 += __shfl_xor_sync(0xffffffffu, s0, off);
            q0 += __shfl_xor_sync(0xffffffffu, q0, off);
            s1 += __shfl_xor_sync(0xffffffffu, s1, off);
            q1 += __shfl_xor_sync(0xffffffffu, q1, off);
        }
        float m0 = s0 * (1.0f/128.0f), m1 = s1 * (1.0f/128.0f);
        float r0 = rsqrtf(q0 * (1.0f/128.0f) - m0*m0 + 1e-5f);
        float r1 = rsqrtf(q1 * (1.0f/128.0f) - m1*m1 + 1e-5f);
        float* a2r0 = sA2 + (warp * 16 + g) * 132;
        float* a2r1 = a2r0 + 8 * 132;
        #pragma unroll
        for (int nt = 0; nt < 16; nt++) {
            *(float2*)(a2r0 + nt*8 + 2*t) =
                make_float2((acc[nt][0]-m0)*r0, (acc[nt][1]-m0)*r0);
            *(float2*)(a2r1 + nt*8 + 2*t) =
                make_float2((acc[nt][2]-m1)*r1, (acc[nt][3]-m1)*r1);
        }
    }
    __syncthreads();

    // ================= GEMM2: 4 chunks, A from sA2 =================
    #pragma unroll
    for (int nt = 0; nt < 16; nt++)
        #pragma unroll
        for (int q = 0; q < 4; q++) acc[nt][q] = 0.0f;

    stageB(g_B2hi, g_B2lo, 0, 0); CP_COMMIT();
    for (int c = 0; c < NC2; c++) {
        int b = c & 1;
        if (c + 1 < NC2) {
            stageB(g_B2hi, g_B2lo, c + 1, b ^ 1);
            CP_COMMIT(); CP_WAIT(1);
        } else {
            CP_WAIT(0);
        }
        __syncthreads();

        uint32_t ahi[4][4], alo[4][4];
        const float* ar0 = sA2 + (warp * 16 + g) * 132 + c * 32;
        const float* ar1 = ar0 + 8 * 132;
        #pragma unroll
        for (int ks = 0; ks < 4; ks++) {
            float v0 = ar0[ks*8 + t],     v1 = ar1[ks*8 + t];
            float v2 = ar0[ks*8 + t + 4], v3 = ar1[ks*8 + t + 4];
            ahi[ks][0] = f2tf(v0); alo[ks][0] = f2tf(v0 - __uint_as_float(ahi[ks][0]));
            ahi[ks][1] = f2tf(v1); alo[ks][1] = f2tf(v1 - __uint_as_float(ahi[ks][1]));
            ahi[ks][2] = f2tf(v2); alo[ks][2] = f2tf(v2 - __uint_as_float(ahi[ks][2]));
            ahi[ks][3] = f2tf(v3); alo[ks][3] = f2tf(v3 - __uint_as_float(ahi[ks][3]));
        }
        const float4* bh4 = (const float4*)(sB + b * 8192);
        const float4* bl4 = (const float4*)(sB + b * 8192 + 4096);
        #pragma unroll
        for (int nt = 0; nt < 16; nt++) {
            float h0[4], h1[4], l0[4], l1[4];
            *(float4*)h0 = bh4[nt*64 + lane];
            *(float4*)h1 = bh4[nt*64 + 32 + lane];
            *(float4*)l0 = bl4[nt*64 + lane];
            *(float4*)l1 = bl4[nt*64 + 32 + lane];
            #pragma unroll
            for (int ks = 0; ks < 4; ks++) {
                uint32_t bh0 = __float_as_uint(h0[ks]), bh1 = __float_as_uint(h1[ks]);
                uint32_t bl0 = __float_as_uint(l0[ks]), bl1 = __float_as_uint(l1[ks]);
                mma8(acc[nt], ahi[ks][0], ahi[ks][1], ahi[ks][2], ahi[ks][3], bh0, bh1);
                mma8(acc[nt], ahi[ks][0], ahi[ks][1], ahi[ks][2], ahi[ks][3], bl0, bl1);
                mma8(acc[nt], alo[ks][0], alo[ks][1], alo[ks][2], alo[ks][3], bh0, bh1);
            }
        }
        __syncthreads();
    }

    // ================= epilogue: stash to smem, coalesced store + bias =================
    {
        float* a2r0 = sA2 + (warp * 16 + g) * 132;
        float* a2r1 = a2r0 + 8 * 132;
        #pragma unroll
        for (int nt = 0; nt < 16; nt++) {
            *(float2*)(a2r0 + nt*8 + 2*t) = make_float2(acc[nt][0], acc[nt][1]);
            *(float2*)(a2r1 + nt*8 + 2*t) = make_float2(acc[nt][2], acc[nt][3]);
        }
    }
    __syncthreads();
    #pragma unroll
    for (int q = 0; q < 16; q++) {
        int idx = tid + 256 * q;          // float4 index in 128x128
        int row = idx >> 5, c4 = idx & 31;
        const float* sv = sA2 + row * 132 + c4 * 4;
        const float* bv = g_pbfold + c4 * 4;
        float4 o;
        o.x = sv[0] + bv[0]; o.y = sv[1] + bv[1];
        o.z = sv[2] + bv[2]; o.w = sv[3] + bv[3];
        *(float4*)(out + (e0 + row) * EDIM + c4 * 4) = o;
    }
}

// ---------------- launch ----------------
extern "C" void kernel_launch(void* const* d_in, const int* in_sizes, int n_in,
                              void* d_out, int out_size) {
    const float* coords = (const float*)d_in[0];
    const float* mask   = (const float*)d_in[1];
    const int*   ri     = (const int*)d_in[2];
    const int*   ci     = (const int*)d_in[3];
    const float* wpw    = (const float*)d_in[4];
    const float* wpb    = (const float*)d_in[5];
    const float* wew    = (const float*)d_in[6];
    const float* lnw    = (const float*)d_in[7];
    const float* lnb    = (const float*)d_in[8];
    const float* pw     = (const float*)d_in[9];
    const float* pb     = (const float*)d_in[10];
    float* out = (float*)d_out;

    long long main_elems = (long long)NEDGE * EDIM;
    float* out_idx = ((long long)out_size > main_elems) ? (out + main_elems) : nullptr;

    cudaFuncSetAttribute(k_fused, cudaFuncAttributeMaxDynamicSharedMemorySize,
                         SM_FLOATS * 4);

    k_backbone<<<(NRES + 255) / 256, 256>>>(coords);
    k_topk<<<NRES, 256>>>(mask, out_idx);
    k_prep<<<((NC1 + NC2) * 4096 + EDIM + 255) / 256, 256>>>(wew, pw, lnw, lnb, pb);
    k_feat<<<(NEDGE * 32) / 256, 256>>>(ri, ci, wpw, wpb);
    k_fused<<<NEDGE / 128, 256, SM_FLOATS * 4>>>(out);
}

// round 5
// speedup vs baseline: 2.5568x; 2.3878x over previous
#include <cuda_runtime.h>
#include <cstdint>

#define NRES 4096
#define KNB  48
#define EDIM 128
#define DFEAT 416
#define NEDGE (NRES*KNB)   // 196608
#define NC1 13             // 416/32 K-chunks for GEMM1
#define NC2 4              // 128/32 K-chunks for GEMM2

typedef unsigned int uint;
typedef unsigned long long ull;

// ---------------- device-global scratch ----------------
__device__ float g_bb[NRES * 15];
__device__ float g_ca[NRES * 3];
__device__ int   g_idx[NEDGE];
__device__ float g_edges[(long long)NEDGE * DFEAT];   // 327 MB
// bf16 2-split weights, pre-packed in m16n8k16 B-fragment layout.
// linear index t = ((c*16 + nt)*2 + ks)*32 + lane -> uint2 {b0, b1}
__device__ __align__(16) uint g_B1hi[NC1 * 2048];
__device__ __align__(16) uint g_B1lo[NC1 * 2048];
__device__ __align__(16) uint g_B2hi[NC2 * 2048];
__device__ __align__(16) uint g_B2lo[NC2 * 2048];
__device__ float g_pbfold[EDIM];                      // pb + pw @ lnb

// ---------------- helpers ----------------
__device__ __forceinline__ uint32_t smaddr(const void* p) {
    return (uint32_t)__cvta_generic_to_shared(p);
}
#define CP16(dst, src) \
    asm volatile("cp.async.cg.shared.global [%0], [%1], 16;" :: "r"(dst), "l"(src))
#define CP_COMMIT() asm volatile("cp.async.commit_group;" ::: "memory")
#define CP_WAIT(n)  asm volatile("cp.async.wait_group %0;" :: "n"(n) : "memory")

// split float2 into packed bf16x2 hi + residual bf16x2 lo
__device__ __forceinline__ void bfsplit(float2 v, uint& h, uint& l) {
    asm("cvt.rn.bf16x2.f32 %0, %1, %2;" : "=r"(h) : "f"(v.y), "f"(v.x));
    float f0 = __uint_as_float(h << 16);
    float f1 = __uint_as_float(h & 0xffff0000u);
    asm("cvt.rn.bf16x2.f32 %0, %1, %2;" : "=r"(l) : "f"(v.y - f1), "f"(v.x - f0));
}

__device__ __forceinline__ void mma16(float* d, uint a0, uint a1, uint a2, uint a3,
                                      uint b0, uint b1) {
    asm volatile(
        "mma.sync.aligned.m16n8k16.row.col.f32.bf16.bf16.f32 "
        "{%0,%1,%2,%3}, {%4,%5,%6,%7}, {%8,%9}, {%0,%1,%2,%3};"
        : "+f"(d[0]), "+f"(d[1]), "+f"(d[2]), "+f"(d[3])
        : "r"(a0), "r"(a1), "r"(a2), "r"(a3), "r"(b0), "r"(b1));
}

// exp(x), x<=0, pure FMA pipe
__device__ __forceinline__ float fexp(float x) {
    x = fmaxf(x, -87.0f);
    float y  = x * 1.4426950408889634f;
    float z  = y + 12582912.0f;
    float nf = z - 12582912.0f;
    float g  = (y - nf) * 0.6931471805599453f;
    float p  = fmaf(g, 1.0f/720.0f, 1.0f/120.0f);
    p = fmaf(g, p, 1.0f/24.0f);
    p = fmaf(g, p, 1.0f/6.0f);
    p = fmaf(g, p, 0.5f);
    p = fmaf(g, p, 1.0f);
    p = fmaf(g, p, 1.0f);
    int n = __float_as_int(z) - 0x4B400000;
    return __int_as_float((n + 127) << 23) * p;
}

// ---------------- kernel 1: backbone ----------------
__global__ void k_backbone(const float* __restrict__ coords) {
    int i = blockIdx.x * blockDim.x + threadIdx.x;
    if (i >= NRES) return;
    const float* p = coords + i * 12;
    float n0=p[0],n1=p[1],n2=p[2];
    float a0=p[3],a1=p[4],a2=p[5];
    float c0=p[6],c1=p[7],c2=p[8];
    float o0=p[9],o1=p[10],o2=p[11];
    float b0=a0-n0, b1=a1-n1, b2=a2-n2;
    float d0=c0-a0, d1=c1-a1, d2=c2-a2;
    float x0 = b1*d2 - b2*d1;
    float x1 = b2*d0 - b0*d2;
    float x2 = b0*d1 - b1*d0;
    float cb0 = -0.58273431f*x0 + 0.56802827f*b0 - 0.54067466f*d0 + a0;
    float cb1 = -0.58273431f*x1 + 0.56802827f*b1 - 0.54067466f*d1 + a1;
    float cb2 = -0.58273431f*x2 + 0.56802827f*b2 - 0.54067466f*d2 + a2;
    float* q = g_bb + i * 15;
    q[0]=n0; q[1]=n1; q[2]=n2;
    q[3]=a0; q[4]=a1; q[5]=a2;
    q[6]=c0; q[7]=c1; q[8]=c2;
    q[9]=o0; q[10]=o1; q[11]=o2;
    q[12]=cb0; q[13]=cb1; q[14]=cb2;
    g_ca[i] = a0; g_ca[NRES + i] = a1; g_ca[2*NRES + i] = a2;
}

// ---------------- kernel 2: exact 48-NN via radix-histogram select ----------------
__global__ __launch_bounds__(256) void k_topk(const float* __restrict__ mask,
                                              float* __restrict__ out_idx) {
    __shared__ float sd[NRES];         // 16 KB
    __shared__ uint  hist[1024];       // 4 KB
    __shared__ ull   cand[2048];       // 16 KB
    __shared__ int   s_thr, s_cnt;
    int i = blockIdx.x, tid = threadIdx.x;

    for (int b = tid; b < 1024; b += 256) hist[b] = 0;
    if (tid == 0) s_cnt = 0;
    float cax = g_ca[i], cay = g_ca[NRES + i], caz = g_ca[2*NRES + i];
    float mi = mask[i];
    __syncthreads();

    for (int j = tid; j < NRES; j += 256) {
        float dx = __fsub_rn(cax, g_ca[j]);
        float dy = __fsub_rn(cay, g_ca[NRES + j]);
        float dz = __fsub_rn(caz, g_ca[2*NRES + j]);
        float d2 = __fadd_rn(__fadd_rn(__fmul_rn(dx,dx), __fmul_rn(dy,dy)), __fmul_rn(dz,dz));
        float dist = __fsqrt_rn(__fadd_rn(d2, 1e-6f));
        if (__fmul_rn(mi, mask[j]) == 0.0f) dist = __int_as_float(0x7f800000);
        sd[j] = dist;
        atomicAdd(&hist[__float_as_uint(dist) >> 21], 1u);
    }
    __syncthreads();

    if (tid == 0) {
        uint cum = 0; int b = 0;
        for (; b < 1024; b++) { cum += hist[b]; if (cum >= KNB) break; }
        s_thr = b;
    }
    __syncthreads();
    uint B = (uint)s_thr;

    for (int j = tid; j < NRES; j += 256) {
        uint bits = __float_as_uint(sd[j]);
        if ((bits >> 21) <= B) {
            int p = atomicAdd(&s_cnt, 1);
            if (p < 2048) cand[p] = ((ull)bits << 32) | (uint)j;
        }
    }
    __syncthreads();

    int C = min(s_cnt, 2048);
    int P = 64; while (P < C) P <<= 1;
    for (int p = C + tid; p < P; p += 256) cand[p] = ~0ULL;
    __syncthreads();

    for (int k = 2; k <= P; k <<= 1)
        for (int j2 = k >> 1; j2 > 0; j2 >>= 1) {
            for (int n = tid; n < P; n += 256) {
                int ixj = n ^ j2;
                if (ixj > n) {
                    ull a = cand[n], c2 = cand[ixj];
                    bool up = ((n & k) == 0);
                    if ((a > c2) == up) { cand[n] = c2; cand[ixj] = a; }
                }
            }
            __syncthreads();
        }

    if (tid < KNB) {
        int j = (int)(cand[tid] & 0xffffffffu);
        g_idx[i * KNB + tid] = j;
        if (out_idx) out_idx[i * KNB + tid] = (float)j;
    }
}

// ---------------- kernel 3: edge features -> g_edges ----------------
__global__ __launch_bounds__(256) void k_feat(const int* __restrict__ ri,
                                              const int* __restrict__ ci,
                                              const float* __restrict__ wpw,
                                              const float* __restrict__ wpb) {
    __shared__ float spd[8][32];
    int gw = (blockIdx.x * 256 + threadIdx.x) >> 5;
    if (gw >= NEDGE) return;
    int lane = threadIdx.x & 31;
    int wIn = threadIdx.x >> 5;
    int i = gw / KNB;
    int j = g_idx[gw];

    if (lane < 25) {
        int a = lane / 5, b = lane % 5;
        float dx = g_bb[i*15 + a*3 + 0] - g_bb[j*15 + b*3 + 0];
        float dy = g_bb[i*15 + a*3 + 1] - g_bb[j*15 + b*3 + 1];
        float dz = g_bb[i*15 + a*3 + 2] - g_bb[j*15 + b*3 + 2];
        spd[wIn][lane] = __fsqrt_rn(dx*dx + dy*dy + dz*dz + 1e-6f);
    }
    __syncwarp();

    float* dst = g_edges + (long long)gw * DFEAT;
    if (lane < 16) {
        int ro = ri[i] - ri[j];
        int enc = (ci[i] == ci[j]) ? min(max(ro + 16, 0), 32) : 33;
        dst[lane] = wpw[lane * 34 + enc] + wpb[lane];
    }
    #pragma unroll
    for (int f = 16 + lane; f < DFEAT; f += 32) {
        int r = f - 16;
        float pd = spd[wIn][r >> 4];
        int bin = r & 15;
        float mu = 2.0f + 1.3333334f * (float)bin;
        float t = (pd - mu) * 0.8f;
        dst[f] = fexp(-t * t);
    }
}

// ---------------- kernel 4: weight prep (bf16 split + fragment pack + folds) ----------------
__global__ __launch_bounds__(256) void k_prep(const float* __restrict__ wew,
                                              const float* __restrict__ pw,
                                              const float* __restrict__ lnw,
                                              const float* __restrict__ lnb,
                                              const float* __restrict__ pb) {
    int t = blockIdx.x * 256 + threadIdx.x;
    const int NB1 = NC1 * 1024;          // uint2 entries
    const int NB2 = NC2 * 1024;
    if (t < NB1) {
        int lane = t & 31, ks = (t >> 5) & 1, nt = (t >> 6) & 15, c = t >> 10;
        int g = lane >> 2, tt = lane & 3;
        int n = nt * 8 + g;
        int k = c * 32 + ks * 16 + 2 * tt;
        const float* src = wew + n * DFEAT;
        uint h0, l0, h1, l1;
        bfsplit(make_float2(src[k],     src[k + 1]), h0, l0);
        bfsplit(make_float2(src[k + 8], src[k + 9]), h1, l1);
        ((uint2*)g_B1hi)[t] = make_uint2(h0, h1);
        ((uint2*)g_B1lo)[t] = make_uint2(l0, l1);
    } else if (t < NB1 + NB2) {
        int t2 = t - NB1;
        int lane = t2 & 31, ks = (t2 >> 5) & 1, nt = (t2 >> 6) & 15, c = t2 >> 10;
        int g = lane >> 2, tt = lane & 3;
        int n = nt * 8 + g;
        int k = c * 32 + ks * 16 + 2 * tt;
        const float* src = pw + n * EDIM;
        uint h0, l0, h1, l1;
        bfsplit(make_float2(src[k] * lnw[k],       src[k + 1] * lnw[k + 1]), h0, l0);
        bfsplit(make_float2(src[k + 8] * lnw[k + 8], src[k + 9] * lnw[k + 9]), h1, l1);
        ((uint2*)g_B2hi)[t2] = make_uint2(h0, h1);
        ((uint2*)g_B2lo)[t2] = make_uint2(l0, l1);
    } else if (t < NB1 + NB2 + EDIM) {
        int f = t - NB1 - NB2;
        float s = pb[f];
        for (int k = 0; k < EDIM; k++) s += pw[f * EDIM + k] * lnb[k];
        g_pbfold[f] = s;
    }
}

// ---------------- kernel 5: fused bf16x2-split MMA GEMM1 + LN + GEMM2 ----------------
// smem floats: sA2 [0, 16896) stride 132 (sA 2x4608 overlaps at [0, 9216))
//              sB  [16896, 25088): 2 buffers x 4096 floats (hi 2048 + lo 2048 packed frags)
//              sRed[25088, 25600): 128 rows x 2 halves x float2
#define SM_SB   16896
#define SM_SRED 25088
#define SM_TOT  25600   // floats -> 102400 bytes, 2 CTAs/SM

__global__ void __launch_bounds__(256, 2) k_fused(float* __restrict__ out) {
    extern __shared__ float sm[];
    float* sA  = sm;                       // GEMM1 A staging (dead after GEMM1)
    float* sA2 = sm;                       // stride-132 matrix (LN result / output stash)
    float* sB  = sm + SM_SB;
    float2* sRed = (float2*)(sm + SM_SRED);

    int tid = threadIdx.x, lane = tid & 31, warp = tid >> 5;
    int g = lane >> 2, tt = lane & 3;
    int mh = warp & 3, nh = warp >> 2;
    long long e0 = (long long)blockIdx.x * 128;

    auto stageA = [&](int c, int b) {
        const float* src = g_edges + e0 * DFEAT + c * 32;
        #pragma unroll
        for (int q = 0; q < 4; q++) {
            int idx = tid + 256 * q;
            int row = idx >> 3, c4 = idx & 7;
            CP16(smaddr(sA + b * 4608 + row * 36 + c4 * 4),
                 src + (long long)row * DFEAT + c4 * 4);
        }
    };
    auto stageB = [&](const uint* hi, const uint* lo, int c, int b) {
        uint4* dst = (uint4*)(sB + b * 4096);
        const uint4* s_hi = (const uint4*)(hi + c * 2048);
        const uint4* s_lo = (const uint4*)(lo + c * 2048);
        #pragma unroll
        for (int q = 0; q < 2; q++) {
            int idx = tid + 256 * q;
            CP16(smaddr(dst + idx),       s_hi + idx);
            CP16(smaddr(dst + 512 + idx), s_lo + idx);
        }
    };

    float acc[2][8][4];
    #pragma unroll
    for (int mt = 0; mt < 2; mt++)
        #pragma unroll
        for (int nt = 0; nt < 8; nt++)
            #pragma unroll
            for (int q = 0; q < 4; q++) acc[mt][nt][q] = 0.0f;

    // ================= GEMM1 =================
    stageA(0, 0); stageB(g_B1hi, g_B1lo, 0, 0); CP_COMMIT();
    for (int c = 0; c < NC1; c++) {
        int b = c & 1;
        if (c + 1 < NC1) {
            stageA(c + 1, b ^ 1); stageB(g_B1hi, g_B1lo, c + 1, b ^ 1);
            CP_COMMIT(); CP_WAIT(1);
        } else {
            CP_WAIT(0);
        }
        __syncthreads();

        uint ah[2][2][4], al[2][2][4];
        #pragma unroll
        for (int mt = 0; mt < 2; mt++) {
            int r0 = mh * 32 + mt * 16 + g;
            #pragma unroll
            for (int ks = 0; ks < 2; ks++) {
                const float* ap = sA + b * 4608 + r0 * 36 + 16 * ks + 2 * tt;
                float2 v0 = *(const float2*)(ap);
                float2 v1 = *(const float2*)(ap + 8 * 36);
                float2 v2 = *(const float2*)(ap + 8);
                float2 v3 = *(const float2*)(ap + 8 * 36 + 8);
                bfsplit(v0, ah[mt][ks][0], al[mt][ks][0]);
                bfsplit(v1, ah[mt][ks][1], al[mt][ks][1]);
                bfsplit(v2, ah[mt][ks][2], al[mt][ks][2]);
                bfsplit(v3, ah[mt][ks][3], al[mt][ks][3]);
            }
        }
        const uint2* bh = (const uint2*)(sB + b * 4096);
        const uint2* bl = bh + 1024;
        #pragma unroll
        for (int nt = 0; nt < 8; nt++) {
            int ntg = nh * 8 + nt;
            uint2 h0 = bh[(ntg * 2 + 0) * 32 + lane];
            uint2 h1 = bh[(ntg * 2 + 1) * 32 + lane];
            uint2 l0 = bl[(ntg * 2 + 0) * 32 + lane];
            uint2 l1 = bl[(ntg * 2 + 1) * 32 + lane];
            #pragma unroll
            for (int mt = 0; mt < 2; mt++) {
                mma16(acc[mt][nt], ah[mt][0][0], ah[mt][0][1], ah[mt][0][2], ah[mt][0][3], h0.x, h0.y);
                mma16(acc[mt][nt], ah[mt][0][0], ah[mt][0][1], ah[mt][0][2], ah[mt][0][3], l0.x, l0.y);
                mma16(acc[mt][nt], al[mt][0][0], al[mt][0][1], al[mt][0][2], al[mt][0][3], h0.x, h0.y);
                mma16(acc[mt][nt], ah[mt][1][0], ah[mt][1][1], ah[mt][1][2], ah[mt][1][3], h1.x, h1.y);
                mma16(acc[mt][nt], ah[mt][1][0], ah[mt][1][1], ah[mt][1][2], ah[mt][1][3], l1.x, l1.y);
                mma16(acc[mt][nt], al[mt][1][0], al[mt][1][1], al[mt][1][2], al[mt][1][3], h1.x, h1.y);
            }
        }
        __syncthreads();
    }

    // prefetch GEMM2 B chunk 0 into sB buffer 0 (free after last sync)
    stageB(g_B2hi, g_B2lo, 0, 0); CP_COMMIT();

    // ================= LayerNorm =================
    {
        float s[2][2], q[2][2];
        #pragma unroll
        for (int mt = 0; mt < 2; mt++) {
            s[mt][0] = s[mt][1] = q[mt][0] = q[mt][1] = 0.f;
            #pragma unroll
            for (int nt = 0; nt < 8; nt++) {
                s[mt][0] += acc[mt][nt][0] + acc[mt][nt][1];
                q[mt][0] += acc[mt][nt][0]*acc[mt][nt][0] + acc[mt][nt][1]*acc[mt][nt][1];
                s[mt][1] += acc[mt][nt][2] + acc[mt][nt][3];
                q[mt][1] += acc[mt][nt][2]*acc[mt][nt][2] + acc[mt][nt][3]*acc[mt][nt][3];
            }
            #pragma unroll
            for (int off = 1; off <= 2; off <<= 1) {
                s[mt][0] += __shfl_xor_sync(0xffffffffu, s[mt][0], off);
                q[mt][0] += __shfl_xor_sync(0xffffffffu, q[mt][0], off);
                s[mt][1] += __shfl_xor_sync(0xffffffffu, s[mt][1], off);
                q[mt][1] += __shfl_xor_sync(0xffffffffu, q[mt][1], off);
            }
        }
        if (tt == 0) {
            #pragma unroll
            for (int mt = 0; mt < 2; mt++)
                #pragma unroll
                for (int rp = 0; rp < 2; rp++) {
                    int r = mh * 32 + mt * 16 + rp * 8 + g;
                    sRed[r * 2 + nh] = make_float2(s[mt][rp], q[mt][rp]);
                }
        }
        __syncthreads();
        float mean[2][2], rstd[2][2];
        #pragma unroll
        for (int mt = 0; mt < 2; mt++)
            #pragma unroll
            for (int rp = 0; rp < 2; rp++) {
                int r = mh * 32 + mt * 16 + rp * 8 + g;
                float2 p0 = sRed[r * 2 + 0], p1 = sRed[r * 2 + 1];
                float S = p0.x + p1.x, Q = p0.y + p1.y;
                float m = S * (1.0f / 128.0f);
                mean[mt][rp] = m;
                rstd[mt][rp] = rsqrtf(Q * (1.0f / 128.0f) - m * m + 1e-5f);
            }
        __syncthreads();   // sA reads fully done before sA2 overwrite (overlap region)
        #pragma unroll
        for (int mt = 0; mt < 2; mt++) {
            int r0 = mh * 32 + mt * 16 + g;
            #pragma unroll
            for (int nt = 0; nt < 8; nt++) {
                int n = (nh * 8 + nt) * 8 + 2 * tt;
                *(float2*)(sA2 + r0 * 132 + n) = make_float2(
                    (acc[mt][nt][0] - mean[mt][0]) * rstd[mt][0],
                    (acc[mt][nt][1] - mean[mt][0]) * rstd[mt][0]);
                *(float2*)(sA2 + (r0 + 8) * 132 + n) = make_float2(
                    (acc[mt][nt][2] - mean[mt][1]) * rstd[mt][1],
                    (acc[mt][nt][3] - mean[mt][1]) * rstd[mt][1]);
            }
        }
    }
    __syncthreads();

    // ================= GEMM2 =================
    #pragma unroll
    for (int mt = 0; mt < 2; mt++)
        #pragma unroll
        for (int nt = 0; nt < 8; nt++)
            #pragma unroll
            for (int q = 0; q < 4; q++) acc[mt][nt][q] = 0.0f;

    for (int c = 0; c < NC2; c++) {
        int b = c & 1;
        if (c + 1 < NC2) {
            stageB(g_B2hi, g_B2lo, c + 1, b ^ 1);
            CP_COMMIT(); CP_WAIT(1);
        } else {
            CP_WAIT(0);
        }
        __syncthreads();

        uint ah[2][2][4], al[2][2][4];
        #pragma unroll
        for (int mt = 0; mt < 2; mt++) {
            int r0 = mh * 32 + mt * 16 + g;
            #pragma unroll
            for (int ks = 0; ks < 2; ks++) {
                const float* ap = sA2 + r0 * 132 + c * 32 + 16 * ks + 2 * tt;
                float2 v0 = *(const float2*)(ap);
                float2 v1 = *(const float2*)(ap + 8 * 132);
                float2 v2 = *(const float2*)(ap + 8);
                float2 v3 = *(const float2*)(ap + 8 * 132 + 8);
                bfsplit(v0, ah[mt][ks][0], al[mt][ks][0]);
                bfsplit(v1, ah[mt][ks][1], al[mt][ks][1]);
                bfsplit(v2, ah[mt][ks][2], al[mt][ks][2]);
                bfsplit(v3, ah[mt][ks][3], al[mt][ks][3]);
            }
        }
        const uint2* bh = (const uint2*)(sB + b * 4096);
        const uint2* bl = bh + 1024;
        #pragma unroll
        for (int nt = 0; nt < 8; nt++) {
            int ntg = nh * 8 + nt;
            uint2 h0 = bh[(ntg * 2 + 0) * 32 + lane];
            uint2 h1 = bh[(ntg * 2 + 1) * 32 + lane];
            uint2 l0 = bl[(ntg * 2 + 0) * 32 + lane];
            uint2 l1 = bl[(ntg * 2 + 1) * 32 + lane];
            #pragma unroll
            for (int mt = 0; mt < 2; mt++) {
                mma16(acc[mt][nt], ah[mt][0][0], ah[mt][0][1], ah[mt][0][2], ah[mt][0][3], h0.x, h0.y);
                mma16(acc[mt][nt], ah[mt][0][0], ah[mt][0][1], ah[mt][0][2], ah[mt][0][3], l0.x, l0.y);
                mma16(acc[mt][nt], al[mt][0][0], al[mt][0][1], al[mt][0][2], al[mt][0][3], h0.x, h0.y);
                mma16(acc[mt][nt], ah[mt][1][0], ah[mt][1][1], ah[mt][1][2], ah[mt][1][3], h1.x, h1.y);
                mma16(acc[mt][nt], ah[mt][1][0], ah[mt][1][1], ah[mt][1][2], ah[mt][1][3], l1.x, l1.y);
                mma16(acc[mt][nt], al[mt][1][0], al[mt][1][1], al[mt][1][2], al[mt][1][3], h1.x, h1.y);
            }
        }
        __syncthreads();
    }

    // ================= epilogue =================
    #pragma unroll
    for (int mt = 0; mt < 2; mt++) {
        int r0 = mh * 32 + mt * 16 + g;
        #pragma unroll
        for (int nt = 0; nt < 8; nt++) {
            int n = (nh * 8 + nt) * 8 + 2 * tt;
            *(float2*)(sA2 + r0 * 132 + n) = make_float2(acc[mt][nt][0], acc[mt][nt][1]);
            *(float2*)(sA2 + (r0 + 8) * 132 + n) = make_float2(acc[mt][nt][2], acc[mt][nt][3]);
        }
    }
    __syncthreads();
    {
        int c4 = tid & 31;
        float4 bias = *(const float4*)(g_pbfold + c4 * 4);
        #pragma unroll
        for (int q = 0; q < 16; q++) {
            int row = (tid >> 5) + 8 * q;
            float4 v = *(const float4*)(sA2 + row * 132 + c4 * 4);
            v.x += bias.x; v.y += bias.y; v.z += bias.z; v.w += bias.w;
            *(float4*)(out + (e0 + row) * EDIM + c4 * 4) = v;
        }
    }
}

// ---------------- launch ----------------
extern "C" void kernel_launch(void* const* d_in, const int* in_sizes, int n_in,
                              void* d_out, int out_size) {
    const float* coords = (const float*)d_in[0];
    const float* mask   = (const float*)d_in[1];
    const int*   ri     = (const int*)d_in[2];
    const int*   ci     = (const int*)d_in[3];
    const float* wpw    = (const float*)d_in[4];
    const float* wpb    = (const float*)d_in[5];
    const float* wew    = (const float*)d_in[6];
    const float* lnw    = (const float*)d_in[7];
    const float* lnb    = (const float*)d_in[8];
    const float* pw     = (const float*)d_in[9];
    const float* pb     = (const float*)d_in[10];
    float* out = (float*)d_out;

    long long main_elems = (long long)NEDGE * EDIM;
    float* out_idx = ((long long)out_size > main_elems) ? (out + main_elems) : nullptr;

    cudaFuncSetAttribute(k_fused, cudaFuncAttributeMaxDynamicSharedMemorySize,
                         SM_TOT * 4);

    k_backbone<<<(NRES + 255) / 256, 256>>>(coords);
    k_topk<<<NRES, 256>>>(mask, out_idx);
    k_prep<<<(NC1 * 1024 + NC2 * 1024 + EDIM + 255) / 256, 256>>>(wew, pw, lnw, lnb, pb);
    k_feat<<<(NEDGE * 32) / 256, 256>>>(ri, ci, wpw, wpb);
    k_fused<<<NEDGE / 128, 256, SM_TOT * 4>>>(out);
}

// round 7
// speedup vs baseline: 2.8241x; 1.1046x over previous
#include <cuda_runtime.h>
#include <cstdint>

#define NRES 4096
#define KNB  48
#define EDIM 128
#define DFEAT 416
#define NEDGE (NRES*KNB)   // 196608
#define NC1 13             // 416/32 K-chunks for GEMM1
#define NC2 4              // 128/32 K-chunks for GEMM2

typedef unsigned int uint;
typedef unsigned long long ull;

// ---------------- device-global scratch ----------------
__device__ float g_bb[NRES * 15];
__device__ float g_ca[NRES * 3];
__device__ int   g_idx[NEDGE];
// bf16 2-split weights, pre-packed in m16n8k16 B-fragment layout.
__device__ __align__(16) uint g_B1hi[NC1 * 2048];
__device__ __align__(16) uint g_B1lo[NC1 * 2048];
__device__ __align__(16) uint g_B2hi[NC2 * 2048];
__device__ __align__(16) uint g_B2lo[NC2 * 2048];
__device__ float g_pbfold[EDIM];                      // pb + pw @ lnb

// ---------------- helpers ----------------
__device__ __forceinline__ uint32_t smaddr(const void* p) {
    return (uint32_t)__cvta_generic_to_shared(p);
}
#define CP16(dst, src) \
    asm volatile("cp.async.cg.shared.global [%0], [%1], 16;" :: "r"(dst), "l"(src))
#define CP_COMMIT() asm volatile("cp.async.commit_group;" ::: "memory")
#define CP_WAIT(n)  asm volatile("cp.async.wait_group %0;" :: "n"(n) : "memory")

// split float2 into packed bf16x2 hi + residual bf16x2 lo
__device__ __forceinline__ void bfsplit(float2 v, uint& h, uint& l) {
    asm("cvt.rn.bf16x2.f32 %0, %1, %2;" : "=r"(h) : "f"(v.y), "f"(v.x));
    float f0 = __uint_as_float(h << 16);
    float f1 = __uint_as_float(h & 0xffff0000u);
    asm("cvt.rn.bf16x2.f32 %0, %1, %2;" : "=r"(l) : "f"(v.y - f1), "f"(v.x - f0));
}

__device__ __forceinline__ void mma16(float* d, uint a0, uint a1, uint a2, uint a3,
                                      uint b0, uint b1) {
    asm volatile(
        "mma.sync.aligned.m16n8k16.row.col.f32.bf16.bf16.f32 "
        "{%0,%1,%2,%3}, {%4,%5,%6,%7}, {%8,%9}, {%0,%1,%2,%3};"
        : "+f"(d[0]), "+f"(d[1]), "+f"(d[2]), "+f"(d[3])
        : "r"(a0), "r"(a1), "r"(a2), "r"(a3), "r"(b0), "r"(b1));
}

// exp(x), x<=0, pure FMA pipe
__device__ __forceinline__ float fexp(float x) {
    x = fmaxf(x, -87.0f);
    float y  = x * 1.4426950408889634f;
    float z  = y + 12582912.0f;
    float nf = z - 12582912.0f;
    float g  = (y - nf) * 0.6931471805599453f;
    float p  = fmaf(g, 1.0f/720.0f, 1.0f/120.0f);
    p = fmaf(g, p, 1.0f/24.0f);
    p = fmaf(g, p, 1.0f/6.0f);
    p = fmaf(g, p, 0.5f);
    p = fmaf(g, p, 1.0f);
    p = fmaf(g, p, 1.0f);
    int n = __float_as_int(z) - 0x4B400000;
    return __int_as_float((n + 127) << 23) * p;
}

// ---------------- kernel 1: backbone ----------------
__global__ void k_backbone(const float* __restrict__ coords) {
    int i = blockIdx.x * blockDim.x + threadIdx.x;
    if (i >= NRES) return;
    const float* p = coords + i * 12;
    float n0=p[0],n1=p[1],n2=p[2];
    float a0=p[3],a1=p[4],a2=p[5];
    float c0=p[6],c1=p[7],c2=p[8];
    float o0=p[9],o1=p[10],o2=p[11];
    float b0=a0-n0, b1=a1-n1, b2=a2-n2;
    float d0=c0-a0, d1=c1-a1, d2=c2-a2;
    float x0 = b1*d2 - b2*d1;
    float x1 = b2*d0 - b0*d2;
    float x2 = b0*d1 - b1*d0;
    float cb0 = -0.58273431f*x0 + 0.56802827f*b0 - 0.54067466f*d0 + a0;
    float cb1 = -0.58273431f*x1 + 0.56802827f*b1 - 0.54067466f*d1 + a1;
    float cb2 = -0.58273431f*x2 + 0.56802827f*b2 - 0.54067466f*d2 + a2;
    float* q = g_bb + i * 15;
    q[0]=n0; q[1]=n1; q[2]=n2;
    q[3]=a0; q[4]=a1; q[5]=a2;
    q[6]=c0; q[7]=c1; q[8]=c2;
    q[9]=o0; q[10]=o1; q[11]=o2;
    q[12]=cb0; q[13]=cb1; q[14]=cb2;
    g_ca[i] = a0; g_ca[NRES + i] = a1; g_ca[2*NRES + i] = a2;
}

// ---------------- kernel 2: exact 48-NN via radix-histogram select ----------------
__global__ __launch_bounds__(256) void k_topk(const float* __restrict__ mask,
                                              float* __restrict__ out_idx) {
    __shared__ float sd[NRES];         // 16 KB
    __shared__ uint  hist[1024];       // 4 KB
    __shared__ ull   cand[2048];       // 16 KB
    __shared__ int   s_thr, s_cnt;
    int i = blockIdx.x, tid = threadIdx.x;

    for (int b = tid; b < 1024; b += 256) hist[b] = 0;
    if (tid == 0) s_cnt = 0;
    float cax = g_ca[i], cay = g_ca[NRES + i], caz = g_ca[2*NRES + i];
    float mi = mask[i];
    __syncthreads();

    for (int j = tid; j < NRES; j += 256) {
        float dx = __fsub_rn(cax, g_ca[j]);
        float dy = __fsub_rn(cay, g_ca[NRES + j]);
        float dz = __fsub_rn(caz, g_ca[2*NRES + j]);
        float d2 = __fadd_rn(__fadd_rn(__fmul_rn(dx,dx), __fmul_rn(dy,dy)), __fmul_rn(dz,dz));
        float dist = __fsqrt_rn(__fadd_rn(d2, 1e-6f));
        if (__fmul_rn(mi, mask[j]) == 0.0f) dist = __int_as_float(0x7f800000);
        sd[j] = dist;
        atomicAdd(&hist[__float_as_uint(dist) >> 21], 1u);
    }
    __syncthreads();

    if (tid == 0) {
        uint cum = 0; int b = 0;
        for (; b < 1024; b++) { cum += hist[b]; if (cum >= KNB) break; }
        s_thr = b;
    }
    __syncthreads();
    uint B = (uint)s_thr;

    for (int j = tid; j < NRES; j += 256) {
        uint bits = __float_as_uint(sd[j]);
        if ((bits >> 21) <= B) {
            int p = atomicAdd(&s_cnt, 1);
            if (p < 2048) cand[p] = ((ull)bits << 32) | (uint)j;
        }
    }
    __syncthreads();

    int C = min(s_cnt, 2048);
    int P = 64; while (P < C) P <<= 1;
    for (int p = C + tid; p < P; p += 256) cand[p] = ~0ULL;
    __syncthreads();

    for (int k = 2; k <= P; k <<= 1)
        for (int j2 = k >> 1; j2 > 0; j2 >>= 1) {
            for (int n = tid; n < P; n += 256) {
                int ixj = n ^ j2;
                if (ixj > n) {
                    ull a = cand[n], c2 = cand[ixj];
                    bool up = ((n & k) == 0);
                    if ((a > c2) == up) { cand[n] = c2; cand[ixj] = a; }
                }
            }
            __syncthreads();
        }

    if (tid < KNB) {
        int j = (int)(cand[tid] & 0xffffffffu);
        g_idx[i * KNB + tid] = j;
        if (out_idx) out_idx[i * KNB + tid] = (float)j;
    }
}

// ---------------- kernel 3: weight prep (bf16 split + fragment pack + folds) ----------------
__global__ __launch_bounds__(256) void k_prep(const float* __restrict__ wew,
                                              const float* __restrict__ pw,
                                              const float* __restrict__ lnw,
                                              const float* __restrict__ lnb,
                                              const float* __restrict__ pb) {
    int t = blockIdx.x * 256 + threadIdx.x;
    const int NB1 = NC1 * 1024;          // uint2 entries
    const int NB2 = NC2 * 1024;
    if (t < NB1) {
        int lane = t & 31, ks = (t >> 5) & 1, nt = (t >> 6) & 15, c = t >> 10;
        int g = lane >> 2, tt = lane & 3;
        int n = nt * 8 + g;
        int k = c * 32 + ks * 16 + 2 * tt;
        const float* src = wew + n * DFEAT;
        uint h0, l0, h1, l1;
        bfsplit(make_float2(src[k],     src[k + 1]), h0, l0);
        bfsplit(make_float2(src[k + 8], src[k + 9]), h1, l1);
        ((uint2*)g_B1hi)[t] = make_uint2(h0, h1);
        ((uint2*)g_B1lo)[t] = make_uint2(l0, l1);
    } else if (t < NB1 + NB2) {
        int t2 = t - NB1;
        int lane = t2 & 31, ks = (t2 >> 5) & 1, nt = (t2 >> 6) & 15, c = t2 >> 10;
        int g = lane >> 2, tt = lane & 3;
        int n = nt * 8 + g;
        int k = c * 32 + ks * 16 + 2 * tt;
        const float* src = pw + n * EDIM;
        uint h0, l0, h1, l1;
        bfsplit(make_float2(src[k] * lnw[k],         src[k + 1] * lnw[k + 1]), h0, l0);
        bfsplit(make_float2(src[k + 8] * lnw[k + 8], src[k + 9] * lnw[k + 9]), h1, l1);
        ((uint2*)g_B2hi)[t2] = make_uint2(h0, h1);
        ((uint2*)g_B2lo)[t2] = make_uint2(l0, l1);
    } else if (t < NB1 + NB2 + EDIM) {
        int f = t - NB1 - NB2;
        float s = pb[f];
        for (int k = 0; k < EDIM; k++) s += pw[f * EDIM + k] * lnb[k];
        g_pbfold[f] = s;
    }
}

// ---------------- kernel 4: fully fused features + GEMM1 + LN + GEMM2 ----------------
// smem floats:
//   sA2  [0, 16896)      : stride-132 LN-result / output stash
//     sA   [0, 9216)     : 2 x 4608 A staging (GEMM1) — dead after GEMM1
//     spd  [9216, 12544) : per-thread 13 pd values — dead after GEMM1
//     swp  [12544, 13120): wpw copy (16x34=544) + wpb (16) + pad
//   sB   [16896, 25088)  : 2 x 4096 packed B fragments
//   sRed [25088, 25600)
#define SM_SPD  9216
#define SM_SWP  12544
#define SM_SB   16896
#define SM_SRED 25088
#define SM_TOT  25600   // floats -> 102400 bytes, 2 CTAs/SM

__global__ void __launch_bounds__(256, 2) k_fused(
    const int* __restrict__ ri, const int* __restrict__ ci,
    const float* __restrict__ wpw, const float* __restrict__ wpb,
    float* __restrict__ out)
{
    extern __shared__ float sm[];
    float* sA  = sm;
    float* sA2 = sm;
    float* spd = sm + SM_SPD;
    float* swp = sm + SM_SWP;
    float* sB  = sm + SM_SB;
    float2* sRed = (float2*)(sm + SM_SRED);

    int tid = threadIdx.x, lane = tid & 31, warp = tid >> 5;
    int g = lane >> 2, tt = lane & 3;
    int mh = warp & 3, nh = warp >> 2;
    long long e0 = (long long)blockIdx.x * 128;

    // ---- prelude: wpw copy, per-thread pd distances, enc ----
    int er = tid >> 1, half = tid & 1;
    int eg = (int)e0 + er;
    int ii = eg / KNB;
    int jj = g_idx[eg];
    for (int q = tid; q < 560; q += 256)
        swp[q] = (q < 544) ? wpw[q] : wpb[q - 544];
    {
        const float* bi = g_bb + ii * 15;
        const float* bj = g_bb + jj * 15;
        for (int c = half ? 0 : 1; c < 13; c++) {
            int p = 2 * c - 1 + half;
            int a = p / 5, b = p % 5;
            float dx = bi[a*3 + 0] - bj[b*3 + 0];
            float dy = bi[a*3 + 1] - bj[b*3 + 1];
            float dz = bi[a*3 + 2] - bj[b*3 + 2];
            spd[tid * 13 + c] = __fsqrt_rn(dx*dx + dy*dy + dz*dz + 1e-6f);
        }
    }
    int enc = 0;
    if (half == 0) {
        int ro = ri[ii] - ri[jj];
        enc = (ci[ii] == ci[jj]) ? min(max(ro + 16, 0), 32) : 33;
    }
    __syncthreads();

    auto fillA = [&](int c, int b) {
        float v[16];
        if (c == 0 && half == 0) {
            #pragma unroll
            for (int q = 0; q < 16; q++)
                v[q] = swp[q * 34 + enc] + swp[544 + q];
        } else {
            float pd = spd[tid * 13 + c];
            #pragma unroll
            for (int q = 0; q < 16; q++) {
                float t = (pd - (2.0f + 1.3333334f * (float)q)) * 0.8f;
                v[q] = fexp(-t * t);
            }
        }
        float* dst = sA + b * 4608 + er * 36 + half * 16;
        #pragma unroll
        for (int q = 0; q < 4; q++)
            *(float4*)(dst + 4 * q) = make_float4(v[4*q], v[4*q+1], v[4*q+2], v[4*q+3]);
    };
    auto stageB = [&](const uint* hi, const uint* lo, int c, int b) {
        uint4* dst = (uint4*)(sB + b * 4096);
        const uint4* s_hi = (const uint4*)(hi + c * 2048);
        const uint4* s_lo = (const uint4*)(lo + c * 2048);
        #pragma unroll
        for (int q = 0; q < 2; q++) {
            int idx = tid + 256 * q;
            CP16(smaddr(dst + idx),       s_hi + idx);
            CP16(smaddr(dst + 512 + idx), s_lo + idx);
        }
    };

    float acc[2][8][4];
    #pragma unroll
    for (int mt = 0; mt < 2; mt++)
        #pragma unroll
        for (int nt = 0; nt < 8; nt++)
            #pragma unroll
            for (int q = 0; q < 4; q++) acc[mt][nt][q] = 0.0f;

    // ================= GEMM1 (double-buffered; TWO barriers per chunk:
    //   S1 after CP_WAIT  : cp.async data + fillA writes visible before reads
    //   S2 after fillA    : all reads of buffer b done before next chunk's
    //                       stageB/prefetch overwrites it (read->write fence)
    // ============================================================
    fillA(0, 0);
    stageB(g_B1hi, g_B1lo, 0, 0); CP_COMMIT();
    for (int c = 0; c < NC1; c++) {
        int b = c & 1;
        if (c + 1 < NC1) { stageB(g_B1hi, g_B1lo, c + 1, b ^ 1); CP_COMMIT(); CP_WAIT(1); }
        else             { CP_WAIT(0); }
        __syncthreads();   // S1

        uint ah[2][2][4], al[2][2][4];
        #pragma unroll
        for (int mt = 0; mt < 2; mt++) {
            int r0 = mh * 32 + mt * 16 + g;
            #pragma unroll
            for (int ks = 0; ks < 2; ks++) {
                const float* ap = sA + b * 4608 + r0 * 36 + 16 * ks + 2 * tt;
                float2 v0 = *(const float2*)(ap);
                float2 v1 = *(const float2*)(ap + 8 * 36);
                float2 v2 = *(const float2*)(ap + 8);
                float2 v3 = *(const float2*)(ap + 8 * 36 + 8);
                bfsplit(v0, ah[mt][ks][0], al[mt][ks][0]);
                bfsplit(v1, ah[mt][ks][1], al[mt][ks][1]);
                bfsplit(v2, ah[mt][ks][2], al[mt][ks][2]);
                bfsplit(v3, ah[mt][ks][3], al[mt][ks][3]);
            }
        }
        const uint2* bh = (const uint2*)(sB + b * 4096);
        const uint2* bl = bh + 1024;
        #pragma unroll
        for (int nt = 0; nt < 8; nt++) {
            int ntg = nh * 8 + nt;
            uint2 h0 = bh[(ntg * 2 + 0) * 32 + lane];
            uint2 h1 = bh[(ntg * 2 + 1) * 32 + lane];
            uint2 l0 = bl[(ntg * 2 + 0) * 32 + lane];
            uint2 l1 = bl[(ntg * 2 + 1) * 32 + lane];
            #pragma unroll
            for (int mt = 0; mt < 2; mt++) {
                mma16(acc[mt][nt], ah[mt][0][0], ah[mt][0][1], ah[mt][0][2], ah[mt][0][3], h0.x, h0.y);
                mma16(acc[mt][nt], ah[mt][0][0], ah[mt][0][1], ah[mt][0][2], ah[mt][0][3], l0.x, l0.y);
                mma16(acc[mt][nt], al[mt][0][0], al[mt][0][1], al[mt][0][2], al[mt][0][3], h0.x, h0.y);
                mma16(acc[mt][nt], ah[mt][1][0], ah[mt][1][1], ah[mt][1][2], ah[mt][1][3], h1.x, h1.y);
                mma16(acc[mt][nt], ah[mt][1][0], ah[mt][1][1], ah[mt][1][2], ah[mt][1][3], l1.x, l1.y);
                mma16(acc[mt][nt], al[mt][1][0], al[mt][1][1], al[mt][1][2], al[mt][1][3], h1.x, h1.y);
            }
        }
        // generate next chunk's A while this chunk's MMAs drain on the tensor pipe
        if (c + 1 < NC1) fillA(c + 1, b ^ 1);
        __syncthreads();   // S2 (read->write fence for sA/sB double buffers)
    }

    // prefetch GEMM2 B chunk 0 (safe: S2 of last chunk fenced all sB reads)
    stageB(g_B2hi, g_B2lo, 0, 0); CP_COMMIT();

    // ================= LayerNorm =================
    {
        float s[2][2], q[2][2];
        #pragma unroll
        for (int mt = 0; mt < 2; mt++) {
            s[mt][0] = s[mt][1] = q[mt][0] = q[mt][1] = 0.f;
            #pragma unroll
            for (int nt = 0; nt < 8; nt++) {
                s[mt][0] += acc[mt][nt][0] + acc[mt][nt][1];
                q[mt][0] += acc[mt][nt][0]*acc[mt][nt][0] + acc[mt][nt][1]*acc[mt][nt][1];
                s[mt][1] += acc[mt][nt][2] + acc[mt][nt][3];
                q[mt][1] += acc[mt][nt][2]*acc[mt][nt][2] + acc[mt][nt][3]*acc[mt][nt][3];
            }
            #pragma unroll
            for (int off = 1; off <= 2; off <<= 1) {
                s[mt][0] += __shfl_xor_sync(0xffffffffu, s[mt][0], off);
                q[mt][0] += __shfl_xor_sync(0xffffffffu, q[mt][0], off);
                s[mt][1] += __shfl_xor_sync(0xffffffffu, s[mt][1], off);
                q[mt][1] += __shfl_xor_sync(0xffffffffu, q[mt][1], off);
            }
        }
        if (tt == 0) {
            #pragma unroll
            for (int mt = 0; mt < 2; mt++)
                #pragma unroll
                for (int rp = 0; rp < 2; rp++) {
                    int r = mh * 32 + mt * 16 + rp * 8 + g;
                    sRed[r * 2 + nh] = make_float2(s[mt][rp], q[mt][rp]);
                }
        }
        __syncthreads();
        float mean[2][2], rstd[2][2];
        #pragma unroll
        for (int mt = 0; mt < 2; mt++)
            #pragma unroll
            for (int rp = 0; rp < 2; rp++) {
                int r = mh * 32 + mt * 16 + rp * 8 + g;
                float2 p0 = sRed[r * 2 + 0], p1 = sRed[r * 2 + 1];
                float S = p0.x + p1.x, Q = p0.y + p1.y;
                float m = S * (1.0f / 128.0f);
                mean[mt][rp] = m;
                rstd[mt][rp] = rsqrtf(Q * (1.0f / 128.0f) - m * m + 1e-5f);
            }
        #pragma unroll
        for (int mt = 0; mt < 2; mt++) {
            int r0 = mh * 32 + mt * 16 + g;
            #pragma unroll
            for (int nt = 0; nt < 8; nt++) {
                int n = (nh * 8 + nt) * 8 + 2 * tt;
                *(float2*)(sA2 + r0 * 132 + n) = make_float2(
                    (acc[mt][nt][0] - mean[mt][0]) * rstd[mt][0],
                    (acc[mt][nt][1] - mean[mt][0]) * rstd[mt][0]);
                *(float2*)(sA2 + (r0 + 8) * 132 + n) = make_float2(
                    (acc[mt][nt][2] - mean[mt][1]) * rstd[mt][1],
                    (acc[mt][nt][3] - mean[mt][1]) * rstd[mt][1]);
            }
        }
    }
    __syncthreads();

    // ================= GEMM2 =================
    #pragma unroll
    for (int mt = 0; mt < 2; mt++)
        #pragma unroll
        for (int nt = 0; nt < 8; nt++)
            #pragma unroll
            for (int q = 0; q < 4; q++) acc[mt][nt][q] = 0.0f;

    for (int c = 0; c < NC2; c++) {
        int b = c & 1;
        if (c + 1 < NC2) { stageB(g_B2hi, g_B2lo, c + 1, b ^ 1); CP_COMMIT(); CP_WAIT(1); }
        else             { CP_WAIT(0); }
        __syncthreads();

        uint ah[2][2][4], al[2][2][4];
        #pragma unroll
        for (int mt = 0; mt < 2; mt++) {
            int r0 = mh * 32 + mt * 16 + g;
            #pragma unroll
            for (int ks = 0; ks < 2; ks++) {
                const float* ap = sA2 + r0 * 132 + c * 32 + 16 * ks + 2 * tt;
                float2 v0 = *(const float2*)(ap);
                float2 v1 = *(const float2*)(ap + 8 * 132);
                float2 v2 = *(const float2*)(ap + 8);
                float2 v3 = *(const float2*)(ap + 8 * 132 + 8);
                bfsplit(v0, ah[mt][ks][0], al[mt][ks][0]);
                bfsplit(v1, ah[mt][ks][1], al[mt][ks][1]);
                bfsplit(v2, ah[mt][ks][2], al[mt][ks][2]);
                bfsplit(v3, ah[mt][ks][3], al[mt][ks][3]);
            }
        }
        const uint2* bh = (const uint2*)(sB + b * 4096);
        const uint2* bl = bh + 1024;
        #pragma unroll
        for (int nt = 0; nt < 8; nt++) {
            int ntg = nh * 8 + nt;
            uint2 h0 = bh[(ntg * 2 + 0) * 32 + lane];
            uint2 h1 = bh[(ntg * 2 + 1) * 32 + lane];
            uint2 l0 = bl[(ntg * 2 + 0) * 32 + lane];
            uint2 l1 = bl[(ntg * 2 + 1) * 32 + lane];
            #pragma unroll
            for (int mt = 0; mt < 2; mt++) {
                mma16(acc[mt][nt], ah[mt][0][0], ah[mt][0][1], ah[mt][0][2], ah[mt][0][3], h0.x, h0.y);
                mma16(acc[mt][nt], ah[mt][0][0], ah[mt][0][1], ah[mt][0][2], ah[mt][0][3], l0.x, l0.y);
                mma16(acc[mt][nt], al[mt][0][0], al[mt][0][1], al[mt][0][2], al[mt][0][3], h0.x, h0.y);
                mma16(acc[mt][nt], ah[mt][1][0], ah[mt][1][1], ah[mt][1][2], ah[mt][1][3], h1.x, h1.y);
                mma16(acc[mt][nt], ah[mt][1][0], ah[mt][1][1], ah[mt][1][2], ah[mt][1][3], l1.x, l1.y);
                mma16(acc[mt][nt], al[mt][1][0], al[mt][1][1], al[mt][1][2], al[mt][1][3], h1.x, h1.y);
            }
        }
        __syncthreads();
    }

    // ================= epilogue =================
    #pragma unroll
    for (int mt = 0; mt < 2; mt++) {
        int r0 = mh * 32 + mt * 16 + g;
        #pragma unroll
        for (int nt = 0; nt < 8; nt++) {
            int n = (nh * 8 + nt) * 8 + 2 * tt;
            *(float2*)(sA2 + r0 * 132 + n) = make_float2(acc[mt][nt][0], acc[mt][nt][1]);
            *(float2*)(sA2 + (r0 + 8) * 132 + n) = make_float2(acc[mt][nt][2], acc[mt][nt][3]);
        }
    }
    __syncthreads();
    {
        int c4 = tid & 31;
        float4 bias = *(const float4*)(g_pbfold + c4 * 4);
        #pragma unroll
        for (int q = 0; q < 16; q++) {
            int row = (tid >> 5) + 8 * q;
            float4 v = *(const float4*)(sA2 + row * 132 + c4 * 4);
            v.x += bias.x; v.y += bias.y; v.z += bias.z; v.w += bias.w;
            *(float4*)(out + (e0 + row) * EDIM + c4 * 4) = v;
        }
    }
}

// ---------------- launch ----------------
extern "C" void kernel_launch(void* const* d_in, const int* in_sizes, int n_in,
                              void* d_out, int out_size) {
    const float* coords = (const float*)d_in[0];
    const float* mask   = (const float*)d_in[1];
    const int*   ri     = (const int*)d_in[2];
    const int*   ci     = (const int*)d_in[3];
    const float* wpw    = (const float*)d_in[4];
    const float* wpb    = (const float*)d_in[5];
    const float* wew    = (const float*)d_in[6];
    const float* lnw    = (const float*)d_in[7];
    const float* lnb    = (const float*)d_in[8];
    const float* pw     = (const float*)d_in[9];
    const float* pb     = (const float*)d_in[10];
    float* out = (float*)d_out;

    long long main_elems = (long long)NEDGE * EDIM;
    float* out_idx = ((long long)out_size > main_elems) ? (out + main_elems) : nullptr;

    cudaFuncSetAttribute(k_fused, cudaFuncAttributeMaxDynamicSharedMemorySize,
                         SM_TOT * 4);

    k_backbone<<<(NRES + 255) / 256, 256>>>(coords);
    k_topk<<<NRES, 256>>>(mask, out_idx);
    k_prep<<<(NC1 * 1024 + NC2 * 1024 + EDIM + 255) / 256, 256>>>(wew, pw, lnw, lnb, pb);
    k_fused<<<NEDGE / 128, 256, SM_TOT * 4>>>(ri, ci, wpw, wpb, out);
}

// round 8
// speedup vs baseline: 2.8848x; 1.0215x over previous
#include <cuda_runtime.h>
#include <cstdint>

#define NRES 4096
#define KNB  48
#define EDIM 128
#define DFEAT 416
#define NEDGE (NRES*KNB)   // 196608
#define NC1 13             // 416/32 K-chunks for GEMM1
#define NC2 4              // 128/32 K-chunks for GEMM2

typedef unsigned int uint;
typedef unsigned long long ull;

// ---------------- device-global scratch ----------------
__device__ float g_bb[NRES * 15];
__device__ float g_ca[NRES * 3];
__device__ int   g_idx[NEDGE];
// bf16 2-split weights, pre-packed in m16n8k16 B-fragment layout.
__device__ __align__(16) uint g_B1hi[NC1 * 2048];
__device__ __align__(16) uint g_B1lo[NC1 * 2048];
__device__ __align__(16) uint g_B2hi[NC2 * 2048];
__device__ __align__(16) uint g_B2lo[NC2 * 2048];
__device__ float g_pbfold[EDIM];                      // pb + pw @ lnb

// ---------------- helpers ----------------
__device__ __forceinline__ uint32_t smaddr(const void* p) {
    return (uint32_t)__cvta_generic_to_shared(p);
}
#define CP16(dst, src) \
    asm volatile("cp.async.cg.shared.global [%0], [%1], 16;" :: "r"(dst), "l"(src))
#define CP_COMMIT() asm volatile("cp.async.commit_group;" ::: "memory")
#define CP_WAIT(n)  asm volatile("cp.async.wait_group %0;" :: "n"(n) : "memory")

// split float2 into packed bf16x2 hi + residual bf16x2 lo
__device__ __forceinline__ void bfsplit(float2 v, uint& h, uint& l) {
    asm("cvt.rn.bf16x2.f32 %0, %1, %2;" : "=r"(h) : "f"(v.y), "f"(v.x));
    float f0 = __uint_as_float(h << 16);
    float f1 = __uint_as_float(h & 0xffff0000u);
    asm("cvt.rn.bf16x2.f32 %0, %1, %2;" : "=r"(l) : "f"(v.y - f1), "f"(v.x - f0));
}

__device__ __forceinline__ void mma16(float* d, uint a0, uint a1, uint a2, uint a3,
                                      uint b0, uint b1) {
    asm volatile(
        "mma.sync.aligned.m16n8k16.row.col.f32.bf16.bf16.f32 "
        "{%0,%1,%2,%3}, {%4,%5,%6,%7}, {%8,%9}, {%0,%1,%2,%3};"
        : "+f"(d[0]), "+f"(d[1]), "+f"(d[2]), "+f"(d[3])
        : "r"(a0), "r"(a1), "r"(a2), "r"(a3), "r"(b0), "r"(b1));
}

// exp(x), x<=0, pure FMA pipe
__device__ __forceinline__ float fexp(float x) {
    x = fmaxf(x, -87.0f);
    float y  = x * 1.4426950408889634f;
    float z  = y + 12582912.0f;
    float nf = z - 12582912.0f;
    float g  = (y - nf) * 0.6931471805599453f;
    float p  = fmaf(g, 1.0f/720.0f, 1.0f/120.0f);
    p = fmaf(g, p, 1.0f/24.0f);
    p = fmaf(g, p, 1.0f/6.0f);
    p = fmaf(g, p, 0.5f);
    p = fmaf(g, p, 1.0f);
    p = fmaf(g, p, 1.0f);
    int n = __float_as_int(z) - 0x4B400000;
    return __int_as_float((n + 127) << 23) * p;
}

// ---------------- kernel 1: backbone ----------------
__global__ void k_backbone(const float* __restrict__ coords) {
    int i = blockIdx.x * blockDim.x + threadIdx.x;
    if (i >= NRES) return;
    const float* p = coords + i * 12;
    float n0=p[0],n1=p[1],n2=p[2];
    float a0=p[3],a1=p[4],a2=p[5];
    float c0=p[6],c1=p[7],c2=p[8];
    float o0=p[9],o1=p[10],o2=p[11];
    float b0=a0-n0, b1=a1-n1, b2=a2-n2;
    float d0=c0-a0, d1=c1-a1, d2=c2-a2;
    float x0 = b1*d2 - b2*d1;
    float x1 = b2*d0 - b0*d2;
    float x2 = b0*d1 - b1*d0;
    float cb0 = -0.58273431f*x0 + 0.56802827f*b0 - 0.54067466f*d0 + a0;
    float cb1 = -0.58273431f*x1 + 0.56802827f*b1 - 0.54067466f*d1 + a1;
    float cb2 = -0.58273431f*x2 + 0.56802827f*b2 - 0.54067466f*d2 + a2;
    float* q = g_bb + i * 15;
    q[0]=n0; q[1]=n1; q[2]=n2;
    q[3]=a0; q[4]=a1; q[5]=a2;
    q[6]=c0; q[7]=c1; q[8]=c2;
    q[9]=o0; q[10]=o1; q[11]=o2;
    q[12]=cb0; q[13]=cb1; q[14]=cb2;
    g_ca[i] = a0; g_ca[NRES + i] = a1; g_ca[2*NRES + i] = a2;
}

// ---------------- kernel 2: exact 48-NN, histogram on d2 (sqrt only for candidates) --------
__global__ __launch_bounds__(256) void k_topk(const float* __restrict__ mask,
                                              float* __restrict__ out_idx) {
    __shared__ float se[NRES];         // e = d2 + 1e-6 (sqrt deferred)
    __shared__ uint  hist[1024];
    __shared__ ull   cand[2048];
    __shared__ int   s_thr, s_cnt;
    int i = blockIdx.x, tid = threadIdx.x;

    for (int b = tid; b < 1024; b += 256) hist[b] = 0;
    if (tid == 0) s_cnt = 0;
    float cax = g_ca[i], cay = g_ca[NRES + i], caz = g_ca[2*NRES + i];
    float mi = mask[i];
    __syncthreads();

    for (int j = tid; j < NRES; j += 256) {
        float dx = __fsub_rn(cax, g_ca[j]);
        float dy = __fsub_rn(cay, g_ca[NRES + j]);
        float dz = __fsub_rn(caz, g_ca[2*NRES + j]);
        float d2 = __fadd_rn(__fadd_rn(__fmul_rn(dx,dx), __fmul_rn(dy,dy)), __fmul_rn(dz,dz));
        float e  = __fadd_rn(d2, 1e-6f);
        if (__fmul_rn(mi, mask[j]) == 0.0f) e = __int_as_float(0x7f800000);
        se[j] = e;
        atomicAdd(&hist[__float_as_uint(e) >> 21], 1u);
    }
    __syncthreads();

    if (tid == 0) {
        uint cum = 0; int b = 0;
        for (; b < 1024; b++) { cum += hist[b]; if (cum >= KNB) break; }
        s_thr = b;
    }
    __syncthreads();
    uint B = (uint)s_thr;

    // e-bins are monotone in dist = sqrt(e); bins differ by >= 2^-3 relative in e,
    // so sqrt values never collide across bins -> candidate set contains true top-48.
    for (int j = tid; j < NRES; j += 256) {
        float e = se[j];
        if ((__float_as_uint(e) >> 21) <= B) {
            int p = atomicAdd(&s_cnt, 1);
            if (p < 2048) {
                float dist = __fsqrt_rn(e);   // exact dist, only for candidates
                cand[p] = ((ull)__float_as_uint(dist) << 32) | (uint)j;
            }
        }
    }
    __syncthreads();

    int C = min(s_cnt, 2048);
    int P = 64; while (P < C) P <<= 1;
    for (int p = C + tid; p < P; p += 256) cand[p] = ~0ULL;
    __syncthreads();

    for (int k = 2; k <= P; k <<= 1)
        for (int j2 = k >> 1; j2 > 0; j2 >>= 1) {
            for (int n = tid; n < P; n += 256) {
                int ixj = n ^ j2;
                if (ixj > n) {
                    ull a = cand[n], c2 = cand[ixj];
                    bool up = ((n & k) == 0);
                    if ((a > c2) == up) { cand[n] = c2; cand[ixj] = a; }
                }
            }
            __syncthreads();
        }

    if (tid < KNB) {
        int j = (int)(cand[tid] & 0xffffffffu);
        g_idx[i * KNB + tid] = j;
        if (out_idx) out_idx[i * KNB + tid] = (float)j;
    }
}

// ---------------- kernel 3: weight prep (bf16 split + fragment pack + folds) ----------------
__global__ __launch_bounds__(256) void k_prep(const float* __restrict__ wew,
                                              const float* __restrict__ pw,
                                              const float* __restrict__ lnw,
                                              const float* __restrict__ lnb,
                                              const float* __restrict__ pb) {
    int t = blockIdx.x * 256 + threadIdx.x;
    const int NB1 = NC1 * 1024;          // uint2 entries
    const int NB2 = NC2 * 1024;
    if (t < NB1) {
        int lane = t & 31, ks = (t >> 5) & 1, nt = (t >> 6) & 15, c = t >> 10;
        int g = lane >> 2, tt = lane & 3;
        int n = nt * 8 + g;
        int k = c * 32 + ks * 16 + 2 * tt;
        const float* src = wew + n * DFEAT;
        uint h0, l0, h1, l1;
        bfsplit(make_float2(src[k],     src[k + 1]), h0, l0);
        bfsplit(make_float2(src[k + 8], src[k + 9]), h1, l1);
        ((uint2*)g_B1hi)[t] = make_uint2(h0, h1);
        ((uint2*)g_B1lo)[t] = make_uint2(l0, l1);
    } else if (t < NB1 + NB2) {
        int t2 = t - NB1;
        int lane = t2 & 31, ks = (t2 >> 5) & 1, nt = (t2 >> 6) & 15, c = t2 >> 10;
        int g = lane >> 2, tt = lane & 3;
        int n = nt * 8 + g;
        int k = c * 32 + ks * 16 + 2 * tt;
        const float* src = pw + n * EDIM;
        uint h0, l0, h1, l1;
        bfsplit(make_float2(src[k] * lnw[k],         src[k + 1] * lnw[k + 1]), h0, l0);
        bfsplit(make_float2(src[k + 8] * lnw[k + 8], src[k + 9] * lnw[k + 9]), h1, l1);
        ((uint2*)g_B2hi)[t2] = make_uint2(h0, h1);
        ((uint2*)g_B2lo)[t2] = make_uint2(l0, l1);
    } else if (t < NB1 + NB2 + EDIM) {
        int f = t - NB1 - NB2;
        float s = pb[f];
        for (int k = 0; k < EDIM; k++) s += pw[f * EDIM + k] * lnb[k];
        g_pbfold[f] = s;
    }
}

// ---------------- kernel 4: fully fused features + GEMM1 + LN + GEMM2 ----------------
// smem floats:
//   sA2  [0, 16896)      : stride-132 LN-result / output stash
//     sA   [0, 9216)     : 2 x 4608 A staging (GEMM1) — dead after GEMM1
//     spd  [9216, 12544) : per-thread 13 pd values — dead after GEMM1
//     swp  [12544, 13120): wpw copy (16x34=544) + wpb (16) + pad
//   sB   [16896, 25088)  : 2 x 4096 packed B fragments (GEMM1 only)
//   sRed [25088, 25600)
#define SM_SPD  9216
#define SM_SWP  12544
#define SM_SB   16896
#define SM_SRED 25088
#define SM_TOT  25600   // floats -> 102400 bytes

__global__ void __launch_bounds__(256, 2) k_fused(
    const int* __restrict__ ri, const int* __restrict__ ci,
    const float* __restrict__ wpw, const float* __restrict__ wpb,
    float* __restrict__ out)
{
    extern __shared__ float sm[];
    float* sA  = sm;
    float* sA2 = sm;
    float* spd = sm + SM_SPD;
    float* swp = sm + SM_SWP;
    float* sB  = sm + SM_SB;
    float2* sRed = (float2*)(sm + SM_SRED);

    int tid = threadIdx.x, lane = tid & 31, warp = tid >> 5;
    int g = lane >> 2, tt = lane & 3;
    int mh = warp & 3, nh = warp >> 2;
    long long e0 = (long long)blockIdx.x * 128;

    // ---- prelude: wpw copy, per-thread pd distances, enc ----
    int er = tid >> 1, half = tid & 1;
    int eg = (int)e0 + er;
    int ii = eg / KNB;
    int jj = g_idx[eg];
    for (int q = tid; q < 560; q += 256)
        swp[q] = (q < 544) ? wpw[q] : wpb[q - 544];
    {
        const float* bi = g_bb + ii * 15;
        const float* bj = g_bb + jj * 15;
        for (int c = half ? 0 : 1; c < 13; c++) {
            int p = 2 * c - 1 + half;
            int a = p / 5, b = p % 5;
            float dx = bi[a*3 + 0] - bj[b*3 + 0];
            float dy = bi[a*3 + 1] - bj[b*3 + 1];
            float dz = bi[a*3 + 2] - bj[b*3 + 2];
            spd[tid * 13 + c] = __fsqrt_rn(dx*dx + dy*dy + dz*dz + 1e-6f);
        }
    }
    int enc = 0;
    if (half == 0) {
        int ro = ri[ii] - ri[jj];
        enc = (ci[ii] == ci[jj]) ? min(max(ro + 16, 0), 32) : 33;
    }

    auto fillA = [&](int c, int b) {
        float v[16];
        if (c == 0 && half == 0) {
            #pragma unroll
            for (int q = 0; q < 16; q++)
                v[q] = swp[q * 34 + enc] + swp[544 + q];
        } else {
            float pd = spd[tid * 13 + c];
            #pragma unroll
            for (int q = 0; q < 16; q++) {
                float t = (pd - (2.0f + 1.3333334f * (float)q)) * 0.8f;
                v[q] = fexp(-t * t);
            }
        }
        float* dst = sA + b * 4608 + er * 36 + half * 16;
        #pragma unroll
        for (int q = 0; q < 4; q++)
            *(float4*)(dst + 4 * q) = make_float4(v[4*q], v[4*q+1], v[4*q+2], v[4*q+3]);
    };
    auto stageB = [&](const uint* hi, const uint* lo, int c, int b) {
        uint4* dst = (uint4*)(sB + b * 4096);
        const uint4* s_hi = (const uint4*)(hi + c * 2048);
        const uint4* s_lo = (const uint4*)(lo + c * 2048);
        #pragma unroll
        for (int q = 0; q < 2; q++) {
            int idx = tid + 256 * q;
            CP16(smaddr(dst + idx),       s_hi + idx);
            CP16(smaddr(dst + 512 + idx), s_lo + idx);
        }
    };

    float acc[2][8][4];
    #pragma unroll
    for (int mt = 0; mt < 2; mt++)
        #pragma unroll
        for (int nt = 0; nt < 8; nt++)
            #pragma unroll
            for (int q = 0; q < 4; q++) acc[mt][nt][q] = 0.0f;

    // ================= GEMM1: ONE barrier per chunk ======================
    // All writes to buffer b^1 (stageB cp.async issue + fillA) occur AFTER
    // S1(c); readers of b^1 (chunk c-1) all passed S1(c). Single barrier is
    // both the write->read fence (via CP_WAIT before it) and read->write fence.
    // =====================================================================
    fillA(0, 0);                              // note: pre-loop; S1 of c=0 publishes it
    stageB(g_B1hi, g_B1lo, 0, 0); CP_COMMIT();
    for (int c = 0; c < NC1; c++) {
        int b = c & 1;
        CP_WAIT(0);
        __syncthreads();   // S1
        if (c + 1 < NC1) { stageB(g_B1hi, g_B1lo, c + 1, b ^ 1); CP_COMMIT(); }

        uint ah[2][2][4], al[2][2][4];
        #pragma unroll
        for (int mt = 0; mt < 2; mt++) {
            int r0 = mh * 32 + mt * 16 + g;
            #pragma unroll
            for (int ks = 0; ks < 2; ks++) {
                const float* ap = sA + b * 4608 + r0 * 36 + 16 * ks + 2 * tt;
                float2 v0 = *(const float2*)(ap);
                float2 v1 = *(const float2*)(ap + 8 * 36);
                float2 v2 = *(const float2*)(ap + 8);
                float2 v3 = *(const float2*)(ap + 8 * 36 + 8);
                bfsplit(v0, ah[mt][ks][0], al[mt][ks][0]);
                bfsplit(v1, ah[mt][ks][1], al[mt][ks][1]);
                bfsplit(v2, ah[mt][ks][2], al[mt][ks][2]);
                bfsplit(v3, ah[mt][ks][3], al[mt][ks][3]);
            }
        }
        const uint2* bh = (const uint2*)(sB + b * 4096);
        const uint2* bl = bh + 1024;
        #pragma unroll
        for (int nt = 0; nt < 8; nt++) {
            int ntg = nh * 8 + nt;
            uint2 h0 = bh[(ntg * 2 + 0) * 32 + lane];
            uint2 h1 = bh[(ntg * 2 + 1) * 32 + lane];
            uint2 l0 = bl[(ntg * 2 + 0) * 32 + lane];
            uint2 l1 = bl[(ntg * 2 + 1) * 32 + lane];
            #pragma unroll
            for (int mt = 0; mt < 2; mt++) {
                mma16(acc[mt][nt], ah[mt][0][0], ah[mt][0][1], ah[mt][0][2], ah[mt][0][3], h0.x, h0.y);
                mma16(acc[mt][nt], ah[mt][0][0], ah[mt][0][1], ah[mt][0][2], ah[mt][0][3], l0.x, l0.y);
                mma16(acc[mt][nt], al[mt][0][0], al[mt][0][1], al[mt][0][2], al[mt][0][3], h0.x, h0.y);
                mma16(acc[mt][nt], ah[mt][1][0], ah[mt][1][1], ah[mt][1][2], ah[mt][1][3], h1.x, h1.y);
                mma16(acc[mt][nt], ah[mt][1][0], ah[mt][1][1], ah[mt][1][2], ah[mt][1][3], l1.x, l1.y);
                mma16(acc[mt][nt], al[mt][1][0], al[mt][1][1], al[mt][1][2], al[mt][1][3], h1.x, h1.y);
            }
        }
        // generate next chunk's A while this chunk's MMAs drain on the tensor pipe
        if (c + 1 < NC1) fillA(c + 1, b ^ 1);
    }

    // ================= LayerNorm =================
    {
        float s[2][2], q[2][2];
        #pragma unroll
        for (int mt = 0; mt < 2; mt++) {
            s[mt][0] = s[mt][1] = q[mt][0] = q[mt][1] = 0.f;
            #pragma unroll
            for (int nt = 0; nt < 8; nt++) {
                s[mt][0] += acc[mt][nt][0] + acc[mt][nt][1];
                q[mt][0] += acc[mt][nt][0]*acc[mt][nt][0] + acc[mt][nt][1]*acc[mt][nt][1];
                s[mt][1] += acc[mt][nt][2] + acc[mt][nt][3];
                q[mt][1] += acc[mt][nt][2]*acc[mt][nt][2] + acc[mt][nt][3]*acc[mt][nt][3];
            }
            #pragma unroll
            for (int off = 1; off <= 2; off <<= 1) {
                s[mt][0] += __shfl_xor_sync(0xffffffffu, s[mt][0], off);
                q[mt][0] += __shfl_xor_sync(0xffffffffu, q[mt][0], off);
                s[mt][1] += __shfl_xor_sync(0xffffffffu, s[mt][1], off);
                q[mt][1] += __shfl_xor_sync(0xffffffffu, q[mt][1], off);
            }
        }
        if (tt == 0) {
            #pragma unroll
            for (int mt = 0; mt < 2; mt++)
                #pragma unroll
                for (int rp = 0; rp < 2; rp++) {
                    int r = mh * 32 + mt * 16 + rp * 8 + g;
                    sRed[r * 2 + nh] = make_float2(s[mt][rp], q[mt][rp]);
                }
        }
        __syncthreads();   // fences last sA reads (chunk 12) AND publishes sRed
        float mean[2][2], rstd[2][2];
        #pragma unroll
        for (int mt = 0; mt < 2; mt++)
            #pragma unroll
            for (int rp = 0; rp < 2; rp++) {
                int r = mh * 32 + mt * 16 + rp * 8 + g;
                float2 p0 = sRed[r * 2 + 0], p1 = sRed[r * 2 + 1];
                float S = p0.x + p1.x, Q = p0.y + p1.y;
                float m = S * (1.0f / 128.0f);
                mean[mt][rp] = m;
                rstd[mt][rp] = rsqrtf(Q * (1.0f / 128.0f) - m * m + 1e-5f);
            }
        #pragma unroll
        for (int mt = 0; mt < 2; mt++) {
            int r0 = mh * 32 + mt * 16 + g;
            #pragma unroll
            for (int nt = 0; nt < 8; nt++) {
                int n = (nh * 8 + nt) * 8 + 2 * tt;
                *(float2*)(sA2 + r0 * 132 + n) = make_float2(
                    (acc[mt][nt][0] - mean[mt][0]) * rstd[mt][0],
                    (acc[mt][nt][1] - mean[mt][0]) * rstd[mt][0]);
                *(float2*)(sA2 + (r0 + 8) * 132 + n) = make_float2(
                    (acc[mt][nt][2] - mean[mt][1]) * rstd[mt][1],
                    (acc[mt][nt][3] - mean[mt][1]) * rstd[mt][1]);
            }
        }
    }
    __syncthreads();

    // ================= GEMM2: B via __ldg from L2, NO barriers in loop =====
    #pragma unroll
    for (int mt = 0; mt < 2; mt++)
        #pragma unroll
        for (int nt = 0; nt < 8; nt++)
            #pragma unroll
            for (int q = 0; q < 4; q++) acc[mt][nt][q] = 0.0f;

    #pragma unroll
    for (int c = 0; c < NC2; c++) {
        uint ah[2][2][4], al[2][2][4];
        #pragma unroll
        for (int mt = 0; mt < 2; mt++) {
            int r0 = mh * 32 + mt * 16 + g;
            #pragma unroll
            for (int ks = 0; ks < 2; ks++) {
                const float* ap = sA2 + r0 * 132 + c * 32 + 16 * ks + 2 * tt;
                float2 v0 = *(const float2*)(ap);
                float2 v1 = *(const float2*)(ap + 8 * 132);
                float2 v2 = *(const float2*)(ap + 8);
                float2 v3 = *(const float2*)(ap + 8 * 132 + 8);
                bfsplit(v0, ah[mt][ks][0], al[mt][ks][0]);
                bfsplit(v1, ah[mt][ks][1], al[mt][ks][1]);
                bfsplit(v2, ah[mt][ks][2], al[mt][ks][2]);
                bfsplit(v3, ah[mt][ks][3], al[mt][ks][3]);
            }
        }
        const uint2* bh = (const uint2*)g_B2hi + c * 1024;
        const uint2* bl = (const uint2*)g_B2lo + c * 1024;
        #pragma unroll
        for (int nt = 0; nt < 8; nt++) {
            int ntg = nh * 8 + nt;
            uint2 h0 = __ldg(bh + (ntg * 2 + 0) * 32 + lane);
            uint2 h1 = __ldg(bh + (ntg * 2 + 1) * 32 + lane);
            uint2 l0 = __ldg(bl + (ntg * 2 + 0) * 32 + lane);
            uint2 l1 = __ldg(bl + (ntg * 2 + 1) * 32 + lane);
            #pragma unroll
            for (int mt = 0; mt < 2; mt++) {
                mma16(acc[mt][nt], ah[mt][0][0], ah[mt][0][1], ah[mt][0][2], ah[mt][0][3], h0.x, h0.y);
                mma16(acc[mt][nt], ah[mt][0][0], ah[mt][0][1], ah[mt][0][2], ah[mt][0][3], l0.x, l0.y);
                mma16(acc[mt][nt], al[mt][0][0], al[mt][0][1], al[mt][0][2], al[mt][0][3], h0.x, h0.y);
                mma16(acc[mt][nt], ah[mt][1][0], ah[mt][1][1], ah[mt][1][2], ah[mt][1][3], h1.x, h1.y);
                mma16(acc[mt][nt], ah[mt][1][0], ah[mt][1][1], ah[mt][1][2], ah[mt][1][3], l1.x, l1.y);
                mma16(acc[mt][nt], al[mt][1][0], al[mt][1][1], al[mt][1][2], al[mt][1][3], h1.x, h1.y);
            }
        }
    }

    // ================= epilogue =================
    __syncthreads();   // all cross-warp sA2 reads (GEMM2) done before overwrite
    #pragma unroll
    for (int mt = 0; mt < 2; mt++) {
        int r0 = mh * 32 + mt * 16 + g;
        #pragma unroll
        for (int nt = 0; nt < 8; nt++) {
            int n = (nh * 8 + nt) * 8 + 2 * tt;
            *(float2*)(sA2 + r0 * 132 + n) = make_float2(acc[mt][nt][0], acc[mt][nt][1]);
            *(float2*)(sA2 + (r0 + 8) * 132 + n) = make_float2(acc[mt][nt][2], acc[mt][nt][3]);
        }
    }
    __syncthreads();
    {
        int c4 = tid & 31;
        float4 bias = *(const float4*)(g_pbfold + c4 * 4);
        #pragma unroll
        for (int q = 0; q < 16; q++) {
            int row = (tid >> 5) + 8 * q;
            float4 v = *(const float4*)(sA2 + row * 132 + c4 * 4);
            v.x += bias.x; v.y += bias.y; v.z += bias.z; v.w += bias.w;
            *(float4*)(out + (e0 + row) * EDIM + c4 * 4) = v;
        }
    }
}

// ---------------- launch ----------------
extern "C" void kernel_launch(void* const* d_in, const int* in_sizes, int n_in,
                              void* d_out, int out_size) {
    const float* coords = (const float*)d_in[0];
    const float* mask   = (const float*)d_in[1];
    const int*   ri     = (const int*)d_in[2];
    const int*   ci     = (const int*)d_in[3];
    const float* wpw    = (const float*)d_in[4];
    const float* wpb    = (const float*)d_in[5];
    const float* wew    = (const float*)d_in[6];
    const float* lnw    = (const float*)d_in[7];
    const float* lnb    = (const float*)d_in[8];
    const float* pw     = (const float*)d_in[9];
    const float* pb     = (const float*)d_in[10];
    float* out = (float*)d_out;

    long long main_elems = (long long)NEDGE * EDIM;
    float* out_idx = ((long long)out_size > main_elems) ? (out + main_elems) : nullptr;

    cudaFuncSetAttribute(k_fused, cudaFuncAttributeMaxDynamicSharedMemorySize,
                         SM_TOT * 4);

    k_backbone<<<(NRES + 255) / 256, 256>>>(coords);
    k_topk<<<NRES, 256>>>(mask, out_idx);
    k_prep<<<(NC1 * 1024 + NC2 * 1024 + EDIM + 255) / 256, 256>>>(wew, pw, lnw, lnb, pb);
    k_fused<<<NEDGE / 128, 256, SM_TOT * 4>>>(ri, ci, wpw, wpb, out);
}

// round 10
// speedup vs baseline: 3.4977x; 1.2125x over previous
#include <cuda_runtime.h>
#include <cstdint>

#define NRES 4096
#define KNB  48
#define EDIM 128
#define DFEAT 416
#define NEDGE (NRES*KNB)   // 196608
#define NC1 13
#define NC2 4
#define TILE 64            // edges per CTA

typedef unsigned int uint;
typedef unsigned long long ull;

// ---------------- device-global scratch ----------------
__device__ float g_bb[NRES * 15];
__device__ float g_ca[NRES * 3];
__device__ int   g_idx[NEDGE];
// bf16 2-split weights, pre-packed in m16n8k16 B-fragment layout.
__device__ __align__(16) uint g_B1hi[NC1 * 2048];
__device__ __align__(16) uint g_B1lo[NC1 * 2048];
__device__ __align__(16) uint g_B2hi[NC2 * 2048];
__device__ __align__(16) uint g_B2lo[NC2 * 2048];
__device__ float g_pbfold[EDIM];

// ---------------- helpers ----------------
__device__ __forceinline__ uint32_t smaddr(const void* p) {
    return (uint32_t)__cvta_generic_to_shared(p);
}
#define CP16(dst, src) \
    asm volatile("cp.async.cg.shared.global [%0], [%1], 16;" :: "r"(dst), "l"(src))
#define CP_COMMIT() asm volatile("cp.async.commit_group;" ::: "memory")
#define CP_WAIT(n)  asm volatile("cp.async.wait_group %0;" :: "n"(n) : "memory")

#define LDMX4(r, addr) \
    asm volatile("ldmatrix.sync.aligned.m8n8.x4.shared.b16 {%0,%1,%2,%3}, [%4];" \
        : "=r"((r)[0]), "=r"((r)[1]), "=r"((r)[2]), "=r"((r)[3]) : "r"(addr))

// split float2 into packed bf16x2 hi + residual bf16x2 lo (v.x -> low half)
__device__ __forceinline__ void bfsplit(float2 v, uint& h, uint& l) {
    asm("cvt.rn.bf16x2.f32 %0, %1, %2;" : "=r"(h) : "f"(v.y), "f"(v.x));
    float f0 = __uint_as_float(h << 16);
    float f1 = __uint_as_float(h & 0xffff0000u);
    asm("cvt.rn.bf16x2.f32 %0, %1, %2;" : "=r"(l) : "f"(v.y - f1), "f"(v.x - f0));
}

__device__ __forceinline__ void mma16(float* d, const uint* a, uint b0, uint b1) {
    asm volatile(
        "mma.sync.aligned.m16n8k16.row.col.f32.bf16.bf16.f32 "
        "{%0,%1,%2,%3}, {%4,%5,%6,%7}, {%8,%9}, {%0,%1,%2,%3};"
        : "+f"(d[0]), "+f"(d[1]), "+f"(d[2]), "+f"(d[3])
        : "r"(a[0]), "r"(a[1]), "r"(a[2]), "r"(a[3]), "r"(b0), "r"(b1));
}

// exp(x), x<=0, pure FMA pipe
__device__ __forceinline__ float fexp(float x) {
    x = fmaxf(x, -87.0f);
    float y  = x * 1.4426950408889634f;
    float z  = y + 12582912.0f;
    float nf = z - 12582912.0f;
    float g  = (y - nf) * 0.6931471805599453f;
    float p  = fmaf(g, 1.0f/720.0f, 1.0f/120.0f);
    p = fmaf(g, p, 1.0f/24.0f);
    p = fmaf(g, p, 1.0f/6.0f);
    p = fmaf(g, p, 0.5f);
    p = fmaf(g, p, 1.0f);
    p = fmaf(g, p, 1.0f);
    int n = __float_as_int(z) - 0x4B400000;
    return __int_as_float((n + 127) << 23) * p;
}

// ---------------- kernel 1: backbone ----------------
__global__ void k_backbone(const float* __restrict__ coords) {
    int i = blockIdx.x * blockDim.x + threadIdx.x;
    if (i >= NRES) return;
    const float* p = coords + i * 12;
    float n0=p[0],n1=p[1],n2=p[2];
    float a0=p[3],a1=p[4],a2=p[5];
    float c0=p[6],c1=p[7],c2=p[8];
    float o0=p[9],o1=p[10],o2=p[11];
    float b0=a0-n0, b1=a1-n1, b2=a2-n2;
    float d0=c0-a0, d1=c1-a1, d2=c2-a2;
    float x0 = b1*d2 - b2*d1;
    float x1 = b2*d0 - b0*d2;
    float x2 = b0*d1 - b1*d0;
    float cb0 = -0.58273431f*x0 + 0.56802827f*b0 - 0.54067466f*d0 + a0;
    float cb1 = -0.58273431f*x1 + 0.56802827f*b1 - 0.54067466f*d1 + a1;
    float cb2 = -0.58273431f*x2 + 0.56802827f*b2 - 0.54067466f*d2 + a2;
    float* q = g_bb + i * 15;
    q[0]=n0; q[1]=n1; q[2]=n2;
    q[3]=a0; q[4]=a1; q[5]=a2;
    q[6]=c0; q[7]=c1; q[8]=c2;
    q[9]=o0; q[10]=o1; q[11]=o2;
    q[12]=cb0; q[13]=cb1; q[14]=cb2;
    g_ca[i] = a0; g_ca[NRES + i] = a1; g_ca[2*NRES + i] = a2;
}

// ---------------- kernel 2: exact 48-NN (parallel threshold scan) ----------------
__global__ __launch_bounds__(256) void k_topk(const float* __restrict__ mask,
                                              float* __restrict__ out_idx) {
    __shared__ float se[NRES];
    __shared__ uint  hist[1024];
    __shared__ ull   cand[2048];
    __shared__ uint  wsum[8];
    __shared__ int   s_thr, s_cnt;
    int i = blockIdx.x, tid = threadIdx.x;
    int lane = tid & 31, wid = tid >> 5;

    for (int b = tid; b < 1024; b += 256) hist[b] = 0;
    if (tid == 0) s_cnt = 0;
    float cax = g_ca[i], cay = g_ca[NRES + i], caz = g_ca[2*NRES + i];
    float mi = mask[i];
    __syncthreads();

    for (int j = tid; j < NRES; j += 256) {
        float dx = __fsub_rn(cax, g_ca[j]);
        float dy = __fsub_rn(cay, g_ca[NRES + j]);
        float dz = __fsub_rn(caz, g_ca[2*NRES + j]);
        float d2 = __fadd_rn(__fadd_rn(__fmul_rn(dx,dx), __fmul_rn(dy,dy)), __fmul_rn(dz,dz));
        float e  = __fadd_rn(d2, 1e-6f);
        if (__fmul_rn(mi, mask[j]) == 0.0f) e = __int_as_float(0x7f800000);
        se[j] = e;
        atomicAdd(&hist[__float_as_uint(e) >> 21], 1u);
    }
    __syncthreads();

    // parallel threshold: each thread owns 4 bins; prefix scan over 256 threads
    {
        int b0 = tid * 4;
        uint s4 = hist[b0] + hist[b0+1] + hist[b0+2] + hist[b0+3];
        uint v = s4;
        #pragma unroll
        for (int off = 1; off < 32; off <<= 1) {
            uint o = __shfl_up_sync(0xffffffffu, v, off);
            if (lane >= off) v += o;
        }
        if (lane == 31) wsum[wid] = v;
        __syncthreads();
        uint basec = 0;
        #pragma unroll
        for (int w = 0; w < 8; w++) if (w < wid) basec += wsum[w];
        uint incl = basec + v;
        uint excl = incl - s4;
        if (excl < KNB && KNB <= incl) {
            uint cum = excl; int b = b0;
            while (cum + hist[b] < KNB) { cum += hist[b]; b++; }
            s_thr = b;
        }
    }
    __syncthreads();
    uint B = (uint)s_thr;

    for (int j = tid; j < NRES; j += 256) {
        float e = se[j];
        if ((__float_as_uint(e) >> 21) <= B) {
            int p = atomicAdd(&s_cnt, 1);
            if (p < 2048) {
                float dist = __fsqrt_rn(e);
                cand[p] = ((ull)__float_as_uint(dist) << 32) | (uint)j;
            }
        }
    }
    __syncthreads();

    int C = min(s_cnt, 2048);
    int P = 64; while (P < C) P <<= 1;
    for (int p = C + tid; p < P; p += 256) cand[p] = ~0ULL;
    __syncthreads();

    for (int k = 2; k <= P; k <<= 1)
        for (int j2 = k >> 1; j2 > 0; j2 >>= 1) {
            for (int n = tid; n < P; n += 256) {
                int ixj = n ^ j2;
                if (ixj > n) {
                    ull a = cand[n], c2 = cand[ixj];
                    bool up = ((n & k) == 0);
                    if ((a > c2) == up) { cand[n] = c2; cand[ixj] = a; }
                }
            }
            __syncthreads();
        }

    if (tid < KNB) {
        int j = (int)(cand[tid] & 0xffffffffu);
        g_idx[i * KNB + tid] = j;
        if (out_idx) out_idx[i * KNB + tid] = (float)j;
    }
}

// ---------------- kernel 3: weight prep (unchanged packing) ----------------
__global__ __launch_bounds__(256) void k_prep(const float* __restrict__ wew,
                                              const float* __restrict__ pw,
                                              const float* __restrict__ lnw,
                                              const float* __restrict__ lnb,
                                              const float* __restrict__ pb) {
    int t = blockIdx.x * 256 + threadIdx.x;
    const int NB1 = NC1 * 1024;
    const int NB2 = NC2 * 1024;
    if (t < NB1) {
        int lane = t & 31, ks = (t >> 5) & 1, nt = (t >> 6) & 15, c = t >> 10;
        int g = lane >> 2, tt = lane & 3;
        int n = nt * 8 + g;
        int k = c * 32 + ks * 16 + 2 * tt;
        const float* src = wew + n * DFEAT;
        uint h0, l0, h1, l1;
        bfsplit(make_float2(src[k],     src[k + 1]), h0, l0);
        bfsplit(make_float2(src[k + 8], src[k + 9]), h1, l1);
        ((uint2*)g_B1hi)[t] = make_uint2(h0, h1);
        ((uint2*)g_B1lo)[t] = make_uint2(l0, l1);
    } else if (t < NB1 + NB2) {
        int t2 = t - NB1;
        int lane = t2 & 31, ks = (t2 >> 5) & 1, nt = (t2 >> 6) & 15, c = t2 >> 10;
        int g = lane >> 2, tt = lane & 3;
        int n = nt * 8 + g;
        int k = c * 32 + ks * 16 + 2 * tt;
        const float* src = pw + n * EDIM;
        uint h0, l0, h1, l1;
        bfsplit(make_float2(src[k] * lnw[k],         src[k + 1] * lnw[k + 1]), h0, l0);
        bfsplit(make_float2(src[k + 8] * lnw[k + 8], src[k + 9] * lnw[k + 9]), h1, l1);
        ((uint2*)g_B2hi)[t2] = make_uint2(h0, h1);
        ((uint2*)g_B2lo)[t2] = make_uint2(l0, l1);
    } else if (t < NB1 + NB2 + EDIM) {
        int f = t - NB1 - NB2;
        float s = pb[f];
        for (int k = 0; k < EDIM; k++) s += pw[f * EDIM + k] * lnb[k];
        g_pbfold[f] = s;
    }
}

// ---------------- kernel 4: fused, 64-edge tiles, 3 CTAs/SM ----------------
// smem (bytes):
//   union [0, 34816):
//     GEMM1 phase: stage 2 buf x (hi 64x40 bf16 + lo) = 20480 | spd 64x26 f = 6656 @20480 | swp 2240 @27136
//     LN->GEMM2:   A2hi 64x136 bf16 @0 (17408), A2lo @17408 (17408)
//     epilogue:    stash 64x132 f @0 (33792)
//   sB  @34816: 2 x 16384
//   sRed@67584: 64 x 4 x float2 = 2048
#define OFF_SPD  20480
#define OFF_SWP  27136
#define OFF_A2L  17408
#define OFF_B    34816
#define OFF_RED  67584
#define SM_TOT   69632

__global__ void __launch_bounds__(256, 3) k_fused(
    const int* __restrict__ ri, const int* __restrict__ ci,
    const float* __restrict__ wpw, const float* __restrict__ wpb,
    float* __restrict__ out)
{
    extern __shared__ char smb[];
    float* spd = (float*)(smb + OFF_SPD);
    float* swp = (float*)(smb + OFF_SWP);
    float2* sRed = (float2*)(smb + OFF_RED);

    int tid = threadIdx.x, lane = tid & 31, warp = tid >> 5;
    int g = lane >> 2, tt = lane & 3;
    int mh = warp & 1, nh = warp >> 1;          // 2 x 4 warp grid
    int ldrow = (lane & 7) + ((lane >> 3) & 1) * 8;   // ldmatrix row-in-tile
    int ldcol = ((lane >> 4) & 1) * 16;               // ldmatrix byte col offset
    int e0 = blockIdx.x * TILE;

    // ---- prelude ----
    int er = tid >> 2, q = tid & 3;
    int eg = e0 + er;
    int ii = eg / KNB;
    int jj = g_idx[eg];
    for (int p = tid; p < 560; p += 256)
        swp[p] = (p < 544) ? wpw[p] : wpb[p - 544];
    for (int p = tid; p < TILE * 25; p += 256) {
        int e = p / 25, pr = p - e * 25;
        int a = pr / 5, b2 = pr - a * 5;
        int ie = (e0 + e) / KNB;
        int je = g_idx[e0 + e];
        const float* bi = g_bb + ie * 15 + a * 3;
        const float* bj = g_bb + je * 15 + b2 * 3;
        float dx = bi[0] - bj[0], dy = bi[1] - bj[1], dz = bi[2] - bj[2];
        spd[e * 26 + pr] = __fsqrt_rn(dx*dx + dy*dy + dz*dz + 1e-6f);
    }
    int enc;
    {
        int ro = ri[ii] - ri[jj];
        enc = (ci[ii] == ci[jj]) ? min(max(ro + 16, 0), 32) : 33;
    }
    __syncthreads();   // publish spd/swp before any fillA reads

    auto fillA = [&](int c, int b) {
        float v[8];
        if (c == 0 && q < 2) {
            #pragma unroll
            for (int j = 0; j < 8; j++) {
                int f = q * 8 + j;
                v[j] = swp[f * 34 + enc] + swp[544 + f];
            }
        } else {
            int pdIdx = 2 * c - 1 + (q >> 1);
            float pd = spd[er * 26 + pdIdx];
            int binBase = (q & 1) * 8;
            #pragma unroll
            for (int j = 0; j < 8; j++) {
                float t = (pd - (2.0f + 1.3333334f * (float)(binBase + j))) * 0.8f;
                v[j] = fexp(-t * t);
            }
        }
        uint h[4], l[4];
        #pragma unroll
        for (int k = 0; k < 4; k++)
            bfsplit(make_float2(v[2*k], v[2*k+1]), h[k], l[k]);
        char* ph = smb + b * 10240 + er * 80 + q * 16;
        *(uint4*)ph          = make_uint4(h[0], h[1], h[2], h[3]);
        *(uint4*)(ph + 5120) = make_uint4(l[0], l[1], l[2], l[3]);
    };
    auto stageB1 = [&](int c, int b) {
        const uint4* shi = (const uint4*)(g_B1hi + c * 2048);
        const uint4* slo = (const uint4*)(g_B1lo + c * 2048);
        uint d = smaddr(smb + OFF_B) + b * 16384;
        CP16(d + tid * 16,          shi + tid);
        CP16(d + 4096 + tid * 16,   shi + 256 + tid);
        CP16(d + 8192 + tid * 16,   slo + tid);
        CP16(d + 12288 + tid * 16,  slo + 256 + tid);
    };

    float acc[2][4][4];
    #pragma unroll
    for (int mt = 0; mt < 2; mt++)
        #pragma unroll
        for (int nt = 0; nt < 4; nt++)
            #pragma unroll
            for (int z = 0; z < 4; z++) acc[mt][nt][z] = 0.0f;

    // ================= GEMM1 =================
    fillA(0, 0);
    stageB1(0, 0); CP_COMMIT();
    for (int c = 0; c < NC1; c++) {
        int b = c & 1;
        CP_WAIT(0);
        __syncthreads();
        if (c + 1 < NC1) { stageB1(c + 1, b ^ 1); CP_COMMIT(); }

        #pragma unroll
        for (int ks = 0; ks < 2; ks++) {
            uint fh[2][4], fl[2][4];
            #pragma unroll
            for (int mt = 0; mt < 2; mt++) {
                uint ad = smaddr(smb) + b * 10240
                        + (mh * 32 + mt * 16 + ldrow) * 80 + ks * 32 + ldcol;
                LDMX4(fh[mt], ad);
                LDMX4(fl[mt], ad + 5120);
            }
            const uint2* bp = (const uint2*)(smb + OFF_B + b * 16384);
            #pragma unroll
            for (int nt = 0; nt < 4; nt++) {
                int idx = ((nh * 4 + nt) * 2 + ks) * 32 + lane;
                uint2 bh = bp[idx];
                uint2 bl = bp[idx + 1024];
                #pragma unroll
                for (int mt = 0; mt < 2; mt++) {
                    mma16(acc[mt][nt], fh[mt], bh.x, bh.y);
                    mma16(acc[mt][nt], fh[mt], bl.x, bl.y);
                    mma16(acc[mt][nt], fl[mt], bh.x, bh.y);
                }
            }
        }
        if (c + 1 < NC1) fillA(c + 1, b ^ 1);
    }

    // ================= LayerNorm -> bf16-presplit A2 =================
    {
        float s[2][2], qq[2][2];
        #pragma unroll
        for (int mt = 0; mt < 2; mt++) {
            s[mt][0] = s[mt][1] = qq[mt][0] = qq[mt][1] = 0.f;
            #pragma unroll
            for (int nt = 0; nt < 4; nt++) {
                s[mt][0]  += acc[mt][nt][0] + acc[mt][nt][1];
                qq[mt][0] += acc[mt][nt][0]*acc[mt][nt][0] + acc[mt][nt][1]*acc[mt][nt][1];
                s[mt][1]  += acc[mt][nt][2] + acc[mt][nt][3];
                qq[mt][1] += acc[mt][nt][2]*acc[mt][nt][2] + acc[mt][nt][3]*acc[mt][nt][3];
            }
            #pragma unroll
            for (int off = 1; off <= 2; off <<= 1) {
                s[mt][0]  += __shfl_xor_sync(0xffffffffu, s[mt][0],  off);
                qq[mt][0] += __shfl_xor_sync(0xffffffffu, qq[mt][0], off);
                s[mt][1]  += __shfl_xor_sync(0xffffffffu, s[mt][1],  off);
                qq[mt][1] += __shfl_xor_sync(0xffffffffu, qq[mt][1], off);
            }
        }
        if (tt == 0) {
            #pragma unroll
            for (int mt = 0; mt < 2; mt++)
                #pragma unroll
                for (int rp = 0; rp < 2; rp++) {
                    int r = mh * 32 + mt * 16 + rp * 8 + g;
                    sRed[r * 4 + nh] = make_float2(s[mt][rp], qq[mt][rp]);
                }
        }
        __syncthreads();   // also fences last GEMM1 stage reads before A2 overwrite
        float mean[2][2], rstd[2][2];
        #pragma unroll
        for (int mt = 0; mt < 2; mt++)
            #pragma unroll
            for (int rp = 0; rp < 2; rp++) {
                int r = mh * 32 + mt * 16 + rp * 8 + g;
                float S = 0.f, Q = 0.f;
                #pragma unroll
                for (int w = 0; w < 4; w++) {
                    float2 pq = sRed[r * 4 + w];
                    S += pq.x; Q += pq.y;
                }
                float m = S * (1.0f / 128.0f);
                mean[mt][rp] = m;
                rstd[mt][rp] = rsqrtf(Q * (1.0f / 128.0f) - m * m + 1e-5f);
            }
        #pragma unroll
        for (int mt = 0; mt < 2; mt++) {
            int r0 = mh * 32 + mt * 16 + g;
            #pragma unroll
            for (int nt = 0; nt < 4; nt++) {
                int C = nh * 32 + nt * 8 + 2 * tt;
                uint h, l;
                bfsplit(make_float2((acc[mt][nt][0] - mean[mt][0]) * rstd[mt][0],
                                    (acc[mt][nt][1] - mean[mt][0]) * rstd[mt][0]), h, l);
                *(uint*)(smb + r0 * 272 + C * 2)           = h;
                *(uint*)(smb + OFF_A2L + r0 * 272 + C * 2) = l;
                bfsplit(make_float2((acc[mt][nt][2] - mean[mt][1]) * rstd[mt][1],
                                    (acc[mt][nt][3] - mean[mt][1]) * rstd[mt][1]), h, l);
                *(uint*)(smb + (r0 + 8) * 272 + C * 2)           = h;
                *(uint*)(smb + OFF_A2L + (r0 + 8) * 272 + C * 2) = l;
            }
        }
    }
    __syncthreads();

    // ================= GEMM2: A via ldmatrix, B via __ldg =================
    #pragma unroll
    for (int mt = 0; mt < 2; mt++)
        #pragma unroll
        for (int nt = 0; nt < 4; nt++)
            #pragma unroll
            for (int z = 0; z < 4; z++) acc[mt][nt][z] = 0.0f;

    #pragma unroll
    for (int c = 0; c < NC2; c++) {
        #pragma unroll
        for (int ks = 0; ks < 2; ks++) {
            uint fh[2][4], fl[2][4];
            #pragma unroll
            for (int mt = 0; mt < 2; mt++) {
                uint ad = smaddr(smb)
                        + (mh * 32 + mt * 16 + ldrow) * 272 + c * 64 + ks * 32 + ldcol;
                LDMX4(fh[mt], ad);
                LDMX4(fl[mt], ad + OFF_A2L);
            }
            #pragma unroll
            for (int nt = 0; nt < 4; nt++) {
                int idx = c * 1024 + ((nh * 4 + nt) * 2 + ks) * 32 + lane;
                uint2 bh = __ldg((const uint2*)g_B2hi + idx);
                uint2 bl = __ldg((const uint2*)g_B2lo + idx);
                #pragma unroll
                for (int mt = 0; mt < 2; mt++) {
                    mma16(acc[mt][nt], fh[mt], bh.x, bh.y);
                    mma16(acc[mt][nt], fh[mt], bl.x, bl.y);
                    mma16(acc[mt][nt], fl[mt], bh.x, bh.y);
                }
            }
        }
    }

    // ================= epilogue =================
    __syncthreads();   // all A2 reads done before stash overwrite
    {
        float* stash = (float*)smb;
        #pragma unroll
        for (int mt = 0; mt < 2; mt++) {
            int r0 = mh * 32 + mt * 16 + g;
            #pragma unroll
            for (int nt = 0; nt < 4; nt++) {
                int C = nh * 32 + nt * 8 + 2 * tt;
                *(float2*)(stash + r0 * 132 + C)       = make_float2(acc[mt][nt][0], acc[mt][nt][1]);
                *(float2*)(stash + (r0 + 8) * 132 + C) = make_float2(acc[mt][nt][2], acc[mt][nt][3]);
            }
        }
    }
    __syncthreads();
    {
        const float* stash = (const float*)smb;
        int c4 = tid & 31;
        float4 bias = *(const float4*)(g_pbfold + c4 * 4);
        #pragma unroll
        for (int z = 0; z < 8; z++) {
            int idx = tid + 256 * z;
            int row = idx >> 5;
            float4 v = *(const float4*)(stash + row * 132 + c4 * 4);
            v.x += bias.x; v.y += bias.y; v.z += bias.z; v.w += bias.w;
            *(float4*)(out + (long long)(e0 + row) * EDIM + c4 * 4) = v;
        }
    }
}

// ---------------- launch ----------------
extern "C" void kernel_launch(void* const* d_in, const int* in_sizes, int n_in,
                              void* d_out, int out_size) {
    const float* coords = (const float*)d_in[0];
    const float* mask   = (const float*)d_in[1];
    const int*   ri     = (const int*)d_in[2];
    const int*   ci     = (const int*)d_in[3];
    const float* wpw    = (const float*)d_in[4];
    const float* wpb    = (const float*)d_in[5];
    const float* wew    = (const float*)d_in[6];
    const float* lnw    = (const float*)d_in[7];
    const float* lnb    = (const float*)d_in[8];
    const float* pw     = (const float*)d_in[9];
    const float* pb     = (const float*)d_in[10];
    float* out = (float*)d_out;

    long long main_elems = (long long)NEDGE * EDIM;
    float* out_idx = ((long long)out_size > main_elems) ? (out + main_elems) : nullptr;

    cudaFuncSetAttribute(k_fused, cudaFuncAttributeMaxDynamicSharedMemorySize, SM_TOT);

    k_backbone<<<(NRES + 255) / 256, 256>>>(coords);
    k_topk<<<NRES, 256>>>(mask, out_idx);
    k_prep<<<(NC1 * 1024 + NC2 * 1024 + EDIM + 255) / 256, 256>>>(wew, pw, lnw, lnb, pb);
    k_fused<<<NEDGE / TILE, 256, SM_TOT>>>(ri, ci, wpw, wpb, out);
}